// round 13
// baseline (speedup 1.0000x reference)
#include <cuda_runtime.h>
#include <cuda_bf16.h>
#include <cuda_fp16.h>
#include <cstdint>

// ---------------------------------------------------------------------------
// Problem constants
// ---------------------------------------------------------------------------
#define BN   8
#define SEQ  2048
#define DIN  1024
#define DM   1024
#define NTOK (BN*SEQ)          // 16384

// ---------------------------------------------------------------------------
// Blocked fp16 operand layout (round-9/12 validated):
//   operand[row, k] stored as 32KB blocks indexed [row/256][k/64].
//   Block: 256 rows x 128B; row = 64 fp16 k-values, SW128-swizzled.
// Round-13: persistent kernels (grid=148); each CTA loops over tiles with a
//   global chunk pipeline that preloads up to 3 chunks of the NEXT tile
//   while the current tile's epilogue runs. No clusters.
// ---------------------------------------------------------------------------
#define SWZ128(off) ((off) ^ (((off) >> 3) & 0x70))

__device__ uint8_t g_Xq[(size_t)NTOK*DIN*2];
__device__ uint8_t g_Xk[(size_t)NTOK*DIN*2];
__device__ uint8_t g_Xv[(size_t)NTOK*DIN*2];
__device__ uint8_t g_Wq[(size_t)DM*DIN*2];
__device__ uint8_t g_Wk[(size_t)DM*DIN*2];
__device__ uint8_t g_Wv[(size_t)DM*DIN*2];
__device__ uint8_t g_Qb[(size_t)NTOK*DM*2];          // 4MB/batch, nkc=16
__device__ uint8_t g_Kb[(size_t)NTOK*DM*2];
__device__ uint8_t g_Vt[(size_t)BN*DM*SEQ*2];        // rows=v, k=s, nkc=32, 4MB/batch
__device__ uint8_t g_Pb[(size_t)BN*SEQ*SEQ*2];       // rows=q, k=s, nkc=32, 8MB/batch
__device__ float   g_rs[(size_t)BN*SEQ];

// ---------------------------------------------------------------------------
// Helpers available on base compute_103
// ---------------------------------------------------------------------------
__device__ __forceinline__ uint32_t smem_u32(const void* p) {
    uint32_t a;
    asm("{ .reg .u64 t; cvta.to.shared.u64 t, %1; cvt.u32.u64 %0, t; }"
        : "=r"(a) : "l"(p));
    return a;
}
__device__ __forceinline__ void cp16(uint32_t dst, const void* src) {
    asm volatile("cp.async.cg.shared.global [%0], [%1], 16;" :: "r"(dst), "l"(src));
}
#define CP_COMMIT()  asm volatile("cp.async.commit_group;" ::: "memory")
#define CP_WAIT(N)   asm volatile("cp.async.wait_group %0;" :: "n"(N) : "memory")

__device__ __forceinline__ void mma16816h(float* c, const uint32_t* a,
                                          uint32_t b0, uint32_t b1) {
    asm volatile(
        "mma.sync.aligned.m16n8k16.row.col.f32.f16.f16.f32 "
        "{%0,%1,%2,%3}, {%4,%5,%6,%7}, {%8,%9}, {%0,%1,%2,%3};"
        : "+f"(c[0]), "+f"(c[1]), "+f"(c[2]), "+f"(c[3])
        : "r"(a[0]), "r"(a[1]), "r"(a[2]), "r"(a[3]), "r"(b0), "r"(b1));
}

__device__ __forceinline__ uint32_t pkh2(__half a, __half b) {
    __half2 t; t.x = a; t.y = b;
    return *(uint32_t*)&t;
}
__device__ __forceinline__ void store_blk1(uint8_t* base, int row, int k,
                                           int nkc, float v) {
    const size_t blk = (((size_t)(row >> 8)) * nkc + (k >> 6)) << 15;
    const uint32_t off = (uint32_t)(row & 255) * 128 + (k & 63) * 2;
    *(__half*)(base + blk + SWZ128(off)) = __float2half(v);
}

// bulk copy (UBLKCP): contiguous gmem -> smem, completion via mbarrier tx-bytes
__device__ __forceinline__ void bulk_ld(uint32_t dst, const void* src,
                                        uint32_t bytes, uint32_t mbar) {
    asm volatile(
        "cp.async.bulk.shared::cluster.global.mbarrier::complete_tx::bytes "
        "[%0], [%1], %2, [%3];"
        :: "r"(dst), "l"(src), "r"(bytes), "r"(mbar) : "memory");
}
#define MBAR_INIT(addr, cnt) \
    asm volatile("mbarrier.init.shared.b64 [%0], %1;" :: "r"((uint32_t)(addr)), "r"((uint32_t)(cnt)) : "memory")
#define MBAR_EXPECT(addr, tx) \
    asm volatile("mbarrier.arrive.expect_tx.shared.b64 _, [%0], %1;" :: "r"((uint32_t)(addr)), "r"((uint32_t)(tx)) : "memory")
#define MBAR_WAIT(mbar, par) do { \
    uint32_t _m = (uint32_t)(mbar), _p = (uint32_t)(par), _d; \
    asm volatile("{\n\t.reg .pred p;\n\t" \
        "mbarrier.try_wait.parity.acquire.cta.shared::cta.b64 p, [%1], %2;\n\t" \
        "selp.b32 %0, 1, 0, p;\n\t}" : "=r"(_d) : "r"(_m), "r"(_p) : "memory"); \
    if (!_d) { \
        asm volatile("{\n\t.reg .pred P1;\n\t" \
            "WL_%=:\n\t" \
            "mbarrier.try_wait.parity.acquire.cta.shared::cta.b64 P1, [%0], %1, 0x989680;\n\t" \
            "@P1 bra.uni WD_%=;\n\tbra.uni WL_%=;\n\tWD_%=:\n\t}" \
            :: "r"(_m), "r"(_p) : "memory"); \
    } \
} while (0)

// ---------------------------------------------------------------------------
// tcgen05 helpers — ONLY compiled when the build has a compute_103a pass.
// ---------------------------------------------------------------------------
#if defined(__CUDA_ARCH_FEAT_SM103_ALL)
#define TCGEN05_ALLOC(a, n) \
    asm volatile("tcgen05.alloc.cta_group::1.sync.aligned.shared::cta.b32 [%0], %1;" \
        :: "r"((uint32_t)(a)), "r"((uint32_t)(n)) : "memory")
#define TCGEN05_RELINQUISH() \
    asm volatile("tcgen05.relinquish_alloc_permit.cta_group::1.sync.aligned;")
#define TCGEN05_DEALLOC(t, n) \
    asm volatile("tcgen05.dealloc.cta_group::1.sync.aligned.b32 %0, %1;" :: "r"(t), "r"((uint32_t)(n)))
#define TCGEN05_COMMIT(m) \
    asm volatile("tcgen05.commit.cta_group::1.mbarrier::arrive::one.shared::cluster.b64 [%0];" \
        :: "r"((uint32_t)(m)) : "memory")
#define TCGEN05_WAIT_LD()     asm volatile("tcgen05.wait::ld.sync.aligned;" ::: "memory")
#define TCGEN05_FENCE_AFTER()  asm volatile("tcgen05.fence::after_thread_sync;" ::: "memory")
#define TCGEN05_FENCE_BEFORE() asm volatile("tcgen05.fence::before_thread_sync;" ::: "memory")
#define TCGEN05_LD_32X32B_X32(r, ta) \
    asm volatile( \
        "tcgen05.ld.sync.aligned.32x32b.x32.b32 " \
        "{%0, %1, %2, %3, %4, %5, %6, %7, " \
        " %8, %9, %10, %11, %12, %13, %14, %15, " \
        " %16, %17, %18, %19, %20, %21, %22, %23, " \
        " %24, %25, %26, %27, %28, %29, %30, %31}, [%32];" \
        : "=r"((r)[0]),  "=r"((r)[1]),  "=r"((r)[2]),  "=r"((r)[3]), \
          "=r"((r)[4]),  "=r"((r)[5]),  "=r"((r)[6]),  "=r"((r)[7]), \
          "=r"((r)[8]),  "=r"((r)[9]),  "=r"((r)[10]), "=r"((r)[11]), \
          "=r"((r)[12]), "=r"((r)[13]), "=r"((r)[14]), "=r"((r)[15]), \
          "=r"((r)[16]), "=r"((r)[17]), "=r"((r)[18]), "=r"((r)[19]), \
          "=r"((r)[20]), "=r"((r)[21]), "=r"((r)[22]), "=r"((r)[23]), \
          "=r"((r)[24]), "=r"((r)[25]), "=r"((r)[26]), "=r"((r)[27]), \
          "=r"((r)[28]), "=r"((r)[29]), "=r"((r)[30]), "=r"((r)[31]) \
        : "r"(ta))
static constexpr uint64_t SMEM_DESC_BASE_SW128 =
    (uint64_t(2)  << 61) | (uint64_t(1) << 46) | (uint64_t(64) << 32) | (uint64_t(1) << 16);
#define MAKE_SMEM_DESC(ba) (SMEM_DESC_BASE_SW128 | ((uint64_t)((ba) >> 4) & 0x3FFF))
__device__ __forceinline__ void mma_f16_ss(uint32_t d, uint64_t ad, uint64_t bd,
                                           uint32_t idesc, bool acc) {
    uint32_t en = acc ? 1u : 0u;
    asm volatile(
        "{\n\t.reg .pred p;\n\t"
        "setp.ne.u32 p, %5, 0;\n\t"
        "tcgen05.mma.cta_group::1.kind::f16 [%0], %1, %2, %3, {%4, %4, %4, %4}, p;\n\t"
        "}"
        :: "r"(d), "l"(ad), "l"(bd), "r"(idesc), "r"(0u), "r"(en)
        : "memory");
}
#endif  // __CUDA_ARCH_FEAT_SM103_ALL

// ---------------------------------------------------------------------------
// Persistent GEMM: C[M,N] = A[M,K] * B[N,K]^T, fp16 blocked operands.
// grid = NPERS CTAs; CTA processes tiles t = blockIdx.x + i*gridDim.x.
// Pipeline uses CTA-local GLOBAL chunk counter: chunk g -> (tile g/NC, kc g%NC);
// loads run up to 3 chunks ahead (crossing tile boundaries -> next tile's
// chunks prefetch during this tile's epilogue). MMA issue of a tile is gated
// behind the previous tile's epilogue (TMEM overwrite hazard).
// MODE 0: dual projection (set = t>>8 selects QK operand set), bias[n], nkc=16
// MODE 2: Vt = Wv * Xv^T (+bias[m]); nkc=32
// MODE 3: e=expf(acc*alpha) f16 out + row-sum atomics, nkc=32
// MODE 4: f32 out = acc / rowsum[m]
// ---------------------------------------------------------------------------
constexpr int OFF_B  = 32768;
constexpr int STAGE  = 65536;                     // 32KB A + 32KB B
constexpr int SMEM_DATA = 1024;
constexpr int SMEM_TOTAL = SMEM_DATA + 3 * STAGE; // 197632
constexpr int NPERS = 148;

template <int MODE>
__device__ __forceinline__ void decode_tile(int t, int& m0, int& n0,
                                            int& zb, int& set) {
    if (MODE == 0)      { set = t >> 8; int r = t & 255; m0 = (r >> 2) << 8; n0 = (r & 3) << 8; zb = 0; }
    else if (MODE == 2) { set = 0; zb = t >> 5; int r = t & 31; m0 = (r >> 3) << 8; n0 = (r & 7) << 8; }
    else if (MODE == 3) { set = 0; zb = t >> 6; int r = t & 63; m0 = (r >> 3) << 8; n0 = (r & 7) << 8; }
    else                { set = 0; zb = t >> 5; int r = t & 31; m0 = (r >> 2) << 8; n0 = (r & 3) << 8; }
}

template <int MODE>
__global__ void __launch_bounds__(256, 1) tc_gemm(
    const uint8_t* __restrict__ Ab, const uint8_t* __restrict__ Bb,
    const uint8_t* __restrict__ A2b, const uint8_t* __restrict__ B2b,
    const float* __restrict__ bias, const float* __restrict__ bias2,
    float* __restrict__ Cf, uint8_t* __restrict__ Cb, uint8_t* __restrict__ C2b,
    float* __restrict__ rs,
    int T, int K, float alpha,
    size_t sAb, size_t sBb, size_t sC)
{
    extern __shared__ char smem[];
    const int tid = threadIdx.x;
    const int NC  = K >> 6;                 // 64-k chunks per tile
    const int myTiles = (T - (int)blockIdx.x + (int)gridDim.x - 1) / (int)gridDim.x;
    if (myTiles <= 0) return;

#if defined(__CUDA_ARCH_FEAT_SM103_ALL)
    // ======================= tcgen05 path (sm_103a) ========================
    const uint32_t sb = smem_u32(smem);

    if (tid < 32) TCGEN05_ALLOC(sb + 0, 512);
    if (tid >= 32 && tid < 64) TCGEN05_RELINQUISH();
    if (tid == 0) {
#pragma unroll
        for (int s = 0; s < 3; ++s) {
            MBAR_INIT(sb + 8  + 8 * s, 1);   // full (tx-based)
            MBAR_INIT(sb + 32 + 8 * s, 1);   // mma done
        }
    }
    __syncthreads();
    uint32_t tmem;
    asm volatile("ld.shared.b32 %0, [%1];" : "=r"(tmem) : "r"(sb + 0));

    constexpr uint32_t IDESC =
        (1u << 4) | ((256 / 8) << 17) | ((128 / 16) << 24);

    // Persistent pipeline state (meaningful on tid 0 only)
    int fph0 = 0, fph1 = 0, fph2 = 0;
    int dph0 = 0, dph1 = 0, dph2 = 0;
    long gl = 0;                       // next CTA-local chunk to load
    const long totalChunks = (long)myTiles * NC;

    // load CTA-local chunk g into stage g%3
    auto load_g = [&](long g) {
        const int i  = (int)(g / NC);
        const int kc = (int)(g - (long)i * NC);
        const int t  = (int)blockIdx.x + i * (int)gridDim.x;
        int m0, n0, zb, set;
        decode_tile<MODE>(t, m0, n0, zb, set);
        const uint8_t* pA = (MODE == 0 && set) ? A2b : Ab;
        const uint8_t* pB = (MODE == 0 && set) ? B2b : Bb;
        pA += (size_t)zb * sAb;
        pB += (size_t)zb * sBb;
        const size_t blkA = (((size_t)(m0 >> 8)) * NC + kc) << 15;
        const size_t blkB = (((size_t)(n0 >> 8)) * NC + kc) << 15;
        const int st = (int)(g % 3);
        const uint32_t full = sb + 8 + 8 * st;
        const uint32_t base = sb + SMEM_DATA + st * STAGE;
        MBAR_EXPECT(full, STAGE);
        bulk_ld(base,         pA + blkA, 32768, full);
        bulk_ld(base + OFF_B, pB + blkB, 32768, full);
    };
    auto fwait = [&](int st) {
        if (st == 0)      { MBAR_WAIT(sb + 8,  fph0); fph0 ^= 1; }
        else if (st == 1) { MBAR_WAIT(sb + 16, fph1); fph1 ^= 1; }
        else              { MBAR_WAIT(sb + 24, fph2); fph2 ^= 1; }
    };
    auto dwait = [&](int st) {
        if (st == 0)      { MBAR_WAIT(sb + 32, dph0); dph0 ^= 1; }
        else if (st == 1) { MBAR_WAIT(sb + 40, dph1); dph1 ^= 1; }
        else              { MBAR_WAIT(sb + 48, dph2); dph2 ^= 1; }
    };

    if (tid == 0) {
        while (gl < totalChunks && gl < 3) { load_g(gl); ++gl; }
    }

    for (int i = 0; i < myTiles; ++i) {
        const int t = (int)blockIdx.x + i * (int)gridDim.x;
        int m0, n0, zb, set;
        decode_tile<MODE>(t, m0, n0, zb, set);

        if (tid == 0) {
            const long base_g = (long)i * NC;
            for (int c = 0; c < NC; ++c) {
                const long g = base_g + c;
                const int st = (int)(g % 3);
                fwait(st);

                const uint32_t sbase = sb + SMEM_DATA + st * STAGE;
                const uint64_t daA0 = MAKE_SMEM_DESC(sbase);
                const uint64_t daA1 = MAKE_SMEM_DESC(sbase + 16384);
                const uint64_t db   = MAKE_SMEM_DESC(sbase + OFF_B);
#pragma unroll
                for (int half = 0; half < 2; ++half) {
                    const uint64_t da = half ? daA1 : daA0;
                    const uint32_t dt = tmem + half * 256;
#pragma unroll
                    for (int ks = 0; ks < 4; ++ks)
                        mma_f16_ss(dt, da + ks * 2, db + ks * 2, IDESC,
                                   !(c == 0 && ks == 0));
                }
                TCGEN05_COMMIT(sb + 32 + 8 * st);

                if (c > 0) {                       // mid-tile done wait
                    const int sp = (int)((g - 1) % 3);
                    dwait(sp);
                    if (gl < totalChunks) { load_g(gl); ++gl; }
                }
            }
            // tile end: wait the last chunk's MMA, fund one more preload
            const long gLast = base_g + NC - 1;
            dwait((int)(gLast % 3));
            if (gl < totalChunks) { load_g(gl); ++gl; }
            // up to 3 chunks of the NEXT tile are now in flight during epilogue
        }
        __syncthreads();
        TCGEN05_FENCE_AFTER();

        // ---- epilogue for tile (m0, n0, zb, set) ----
        {
            const int half = tid >> 7;
            const int w4   = (tid >> 5) & 3;
            const int lid  = tid & 31;
            const int m    = m0 + half * 128 + w4 * 32 + lid;
            const uint32_t dt = tmem + half * 256;
            const float* bsp = (MODE == 0 && set) ? bias2 : bias;
            uint8_t* Cbp     = (MODE == 0 && set) ? C2b : Cb;
            float inv = 1.0f, lsum = 0.0f, bm = 0.0f;
            if (MODE == 4) inv = 1.0f / rs[(size_t)zb * SEQ + m];
            if (MODE == 2) bm  = bsp[m];
            for (int j0 = 0; j0 < 256; j0 += 64) {
                uint32_t r[64];
                TCGEN05_LD_32X32B_X32(r,      dt + j0);
                TCGEN05_LD_32X32B_X32(r + 32, dt + j0 + 32);
                TCGEN05_WAIT_LD();
                if (MODE == 4) {
                    float4* dst = (float4*)(Cf + (size_t)zb * sC + (size_t)m * DM + n0 + j0);
#pragma unroll
                    for (int ii = 0; ii < 16; ++ii) {
                        float4 v;
                        v.x = __uint_as_float(r[4 * ii + 0]) * inv;
                        v.y = __uint_as_float(r[4 * ii + 1]) * inv;
                        v.z = __uint_as_float(r[4 * ii + 2]) * inv;
                        v.w = __uint_as_float(r[4 * ii + 3]) * inv;
                        dst[ii] = v;
                    }
                } else {
                    uint32_t H[32];
#pragma unroll
                    for (int ii = 0; ii < 64; ii += 2) {
                        float v0, v1;
                        if (MODE == 3) {
                            v0 = __expf(__uint_as_float(r[ii])     * alpha);
                            v1 = __expf(__uint_as_float(r[ii + 1]) * alpha);
                            lsum += v0 + v1;
                        } else if (MODE == 0) {
                            v0 = __uint_as_float(r[ii])     + bsp[n0 + j0 + ii];
                            v1 = __uint_as_float(r[ii + 1]) + bsp[n0 + j0 + ii + 1];
                        } else {
                            v0 = __uint_as_float(r[ii])     + bm;
                            v1 = __uint_as_float(r[ii + 1]) + bm;
                        }
                        H[ii >> 1] = pkh2(__float2half(v0), __float2half(v1));
                    }
                    uint8_t* obase;
                    size_t blk;
                    const int row = m & 255;
                    if (MODE == 0) {
                        obase = Cbp + (size_t)(m >> 11) * 4194304u;
                        blk   = ((((size_t)((m & 2047) >> 8)) * 16) + ((n0 + j0) >> 6)) << 15;
                    } else if (MODE == 3) {
                        obase = Cbp + (size_t)zb * 8388608u;
                        blk   = ((((size_t)(m >> 8)) * 32) + ((n0 + j0) >> 6)) << 15;
                    } else {
                        obase = Cbp + (size_t)zb * 4194304u;
                        blk   = ((((size_t)(m >> 8)) * 32) + ((n0 + j0) >> 6)) << 15;
                    }
#pragma unroll
                    for (int q = 0; q < 8; ++q) {
                        uint4 hv;
                        hv.x = H[4*q]; hv.y = H[4*q+1]; hv.z = H[4*q+2]; hv.w = H[4*q+3];
                        *(uint4*)(obase + blk +
                                  SWZ128((uint32_t)row * 128 + q * 16)) = hv;
                    }
                }
            }
            if (MODE == 3) atomicAdd(&rs[(size_t)zb * SEQ + m], lsum);
        }
        TCGEN05_FENCE_BEFORE();
        __syncthreads();          // TMEM reads complete before next tile's MMAs
    }
    if (tid < 32) TCGEN05_DEALLOC(tmem, 512);

#elif defined(__CUDA_ARCH__)
    // ================= mma.sync fallback (base compute_103) =================
    // Correctness insurance only (sm_103a cubin is the one that runs).
    constexpr int STR = 20;
    constexpr int TILE_W = 128 * STR;
    constexpr int STAGE_W = 2 * TILE_W;
    const uint32_t sbase = smem_u32(smem);
    const int lane = tid & 31, wid = tid >> 5;
    const int wm = wid >> 1, wn = wid & 1;
    const int g = lane >> 2, tg = lane & 3;
    const int NC32 = K >> 5;

    for (int it = 0; it < myTiles; ++it) {
        const int t = (int)blockIdx.x + it * (int)gridDim.x;
        int m0, n0, zb, set;
        decode_tile<MODE>(t, m0, n0, zb, set);
        const uint8_t* pA = (MODE == 0 && set) ? A2b : Ab;
        const uint8_t* pB = (MODE == 0 && set) ? B2b : Bb;
        const float* bsp  = (MODE == 0 && set) ? bias2 : bias;
        uint8_t* Cbp      = (MODE == 0 && set) ? C2b : Cb;
        pA += (size_t)zb * sAb;
        pB += (size_t)zb * sBb;

        auto load_chunk = [&](int c32, int st, int mbase, int nbase) {
            const int q = tid & 3, r0 = tid >> 2;
            const uint32_t dst0 = sbase + st * STAGE_W * 4;
            const int kc = c32 >> 1, h = c32 & 1;
#pragma unroll
            for (int i = 0; i < 2; ++i) {
                const int ra = mbase + r0 + 64 * i;
                const int rb = nbase + r0 + 64 * i;
                const uint32_t ro = (uint32_t)((r0 + 64 * i) * STR + q * 4) * 4;
                const size_t ba = (((size_t)(ra >> 8)) * NC + kc) << 15;
                const size_t bb = (((size_t)(rb >> 8)) * NC + kc) << 15;
                const uint32_t oa = (uint32_t)(ra & 255) * 128 + h * 64 + q * 16;
                const uint32_t ob = (uint32_t)(rb & 255) * 128 + h * 64 + q * 16;
                cp16(dst0 + ro,              pA + ba + SWZ128(oa));
                cp16(dst0 + TILE_W * 4 + ro, pB + bb + SWZ128(ob));
            }
        };

        for (int mh = 0; mh < 2; ++mh) {
            const int mb0 = m0 + mh * 128;
            for (int np = 0; np < 2; ++np) {
                const int nb0 = n0 + np * 128;

                float acc[2][8][4];
#pragma unroll
                for (int a = 0; a < 2; ++a)
#pragma unroll
                    for (int b = 0; b < 8; ++b)
#pragma unroll
                        for (int c = 0; c < 4; ++c) acc[a][b][c] = 0.0f;

                load_chunk(0, 0, mb0, nb0); CP_COMMIT();

                for (int c = 0; c < NC32; ++c) {
                    const int st = c & 1;
                    if (c + 1 < NC32) { load_chunk(c + 1, st ^ 1, mb0, nb0); CP_COMMIT(); CP_WAIT(1); }
                    else              { CP_WAIT(0); }
                    __syncthreads();

                    const uint32_t* s0 = (const uint32_t*)smem + st * STAGE_W;
#pragma unroll
                    for (int ks = 0; ks < 2; ++ks) {
                        uint32_t af[2][4];
#pragma unroll
                        for (int mt = 0; mt < 2; ++mt) {
                            const int rb = wm * 32 + mt * 16;
                            const uint32_t* pa = s0 + (rb + g) * STR + ks * 8 + tg;
                            af[mt][0] = pa[0];           af[mt][2] = pa[4];
                            af[mt][1] = pa[8 * STR];     af[mt][3] = pa[8 * STR + 4];
                        }
#pragma unroll
                        for (int nt = 0; nt < 8; ++nt) {
                            const int nb = wn * 64 + nt * 8;
                            const uint32_t* pb = s0 + TILE_W + (nb + g) * STR + ks * 8 + tg;
                            const uint32_t b0 = pb[0], b1 = pb[4];
#pragma unroll
                            for (int mt = 0; mt < 2; ++mt)
                                mma16816h(acc[mt][nt], af[mt], b0, b1);
                        }
                    }
                    __syncthreads();
                }

#pragma unroll
                for (int mt = 0; mt < 2; ++mt) {
#pragma unroll
                    for (int nt = 0; nt < 8; ++nt) {
                        const int m1 = mb0 + wm * 32 + mt * 16 + g;
                        const int m2 = m1 + 8;
                        const int n  = nb0 + wn * 64 + nt * 8 + tg * 2;
                        const float* a = acc[mt][nt];
                        if (MODE == 4) {
                            const float i1 = 1.0f / rs[(size_t)zb * SEQ + m1];
                            const float i2 = 1.0f / rs[(size_t)zb * SEQ + m2];
                            float2 v0; v0.x = a[0] * i1; v0.y = a[1] * i1;
                            float2 v1; v1.x = a[2] * i2; v1.y = a[3] * i2;
                            *(float2*)(Cf + (size_t)zb * sC + (size_t)m1 * DM + n) = v0;
                            *(float2*)(Cf + (size_t)zb * sC + (size_t)m2 * DM + n) = v1;
                        } else if (MODE == 0) {
#pragma unroll
                            for (int e = 0; e < 4; ++e) {
                                const int m = (e < 2) ? m1 : m2;
                                const int nn = n + (e & 1);
                                store_blk1(Cbp + (size_t)(m >> 11) * 4194304u,
                                           m & 2047, nn, 16, a[e] + bsp[nn]);
                            }
                        } else if (MODE == 3) {
                            float e0 = __expf(a[0] * alpha), e1 = __expf(a[1] * alpha);
                            float e2 = __expf(a[2] * alpha), e3 = __expf(a[3] * alpha);
                            atomicAdd(&rs[(size_t)zb * SEQ + m1], e0 + e1);
                            atomicAdd(&rs[(size_t)zb * SEQ + m2], e2 + e3);
                            uint8_t* obase = Cbp + (size_t)zb * 8388608u;
                            store_blk1(obase, m1, n,     32, e0);
                            store_blk1(obase, m1, n + 1, 32, e1);
                            store_blk1(obase, m2, n,     32, e2);
                            store_blk1(obase, m2, n + 1, 32, e3);
                        } else {
                            uint8_t* obase = Cbp + (size_t)zb * 4194304u;
#pragma unroll
                            for (int e = 0; e < 4; ++e) {
                                const int m = (e < 2) ? m1 : m2;
                                const int nn = n + (e & 1);
                                store_blk1(obase, m, nn, 32, a[e] + bsp[m]);
                            }
                        }
                    }
                }
                __syncthreads();
            }
        }
    }
#endif
}

// ---------------------------------------------------------------------------
// f32 -> blocked fp16 (K fixed = 1024; nkc = 16). z selects among 3 tensors.
// ---------------------------------------------------------------------------
__global__ void __launch_bounds__(256) split3_k(
    const float* __restrict__ x0, const float* __restrict__ x1,
    const float* __restrict__ x2,
    uint8_t* __restrict__ d0, uint8_t* __restrict__ d1,
    uint8_t* __restrict__ d2, int nunits)
{
    const int z = blockIdx.z;
    const float* x = (z == 0) ? x0 : (z == 1) ? x1 : x2;
    uint8_t*   dst = (z == 0) ? d0 : (z == 1) ? d1 : d2;
    for (int u = blockIdx.x * 256 + threadIdx.x; u < nunits; u += gridDim.x * 256) {
        const int r = u >> 7;
        const int j = u & 127;
        const float4 f0 = *(const float4*)(x + ((size_t)r << 10) + (j << 3));
        const float4 f1 = *(const float4*)(x + ((size_t)r << 10) + (j << 3) + 4);
        uint4 hv;
        hv.x = pkh2(__float2half(f0.x), __float2half(f0.y));
        hv.y = pkh2(__float2half(f0.z), __float2half(f0.w));
        hv.z = pkh2(__float2half(f1.x), __float2half(f1.y));
        hv.w = pkh2(__float2half(f1.z), __float2half(f1.w));
        const size_t blk = ((((size_t)(r >> 8)) << 4) + (j >> 3)) << 15;  // nkc=16
        const uint32_t ro = (uint32_t)(r & 255) * 128 + (j & 7) * 16;
        *(uint4*)(dst + blk + SWZ128(ro)) = hv;
    }
}

__global__ void __launch_bounds__(1024) zero_k(float* __restrict__ p, int n)
{
    int i = blockIdx.x * 1024 + threadIdx.x;
    if (i < n) p[i] = 0.0f;
}

// ---------------------------------------------------------------------------
extern "C" void kernel_launch(void* const* d_in, const int* in_sizes, int n_in,
                              void* d_out, int out_size)
{
    (void)in_sizes; (void)n_in; (void)out_size;
    const float* q  = (const float*)d_in[0];
    const float* kx = (const float*)d_in[1];
    const float* vx = (const float*)d_in[2];
    const float* Wq = (const float*)d_in[3];
    const float* bq = (const float*)d_in[4];
    const float* Wk = (const float*)d_in[5];
    const float* bk = (const float*)d_in[6];
    const float* Wv = (const float*)d_in[7];
    const float* bv = (const float*)d_in[8];
    float* out = (float*)d_out;

    uint8_t *Xq, *Xk, *Xv, *Wqb, *Wkb, *Wvb, *Qb, *Kb, *Vt, *Pb;
    float* rs;
    cudaGetSymbolAddress((void**)&Xq,  g_Xq);  cudaGetSymbolAddress((void**)&Xk,  g_Xk);
    cudaGetSymbolAddress((void**)&Xv,  g_Xv);
    cudaGetSymbolAddress((void**)&Wqb, g_Wq);  cudaGetSymbolAddress((void**)&Wkb, g_Wk);
    cudaGetSymbolAddress((void**)&Wvb, g_Wv);
    cudaGetSymbolAddress((void**)&Qb,  g_Qb);  cudaGetSymbolAddress((void**)&Kb,  g_Kb);
    cudaGetSymbolAddress((void**)&Vt,  g_Vt);  cudaGetSymbolAddress((void**)&Pb,  g_Pb);
    cudaGetSymbolAddress((void**)&rs,  g_rs);

    cudaFuncSetAttribute(tc_gemm<0>, cudaFuncAttributeMaxDynamicSharedMemorySize, SMEM_TOTAL);
    cudaFuncSetAttribute(tc_gemm<2>, cudaFuncAttributeMaxDynamicSharedMemorySize, SMEM_TOTAL);
    cudaFuncSetAttribute(tc_gemm<3>, cudaFuncAttributeMaxDynamicSharedMemorySize, SMEM_TOTAL);
    cudaFuncSetAttribute(tc_gemm<4>, cudaFuncAttributeMaxDynamicSharedMemorySize, SMEM_TOTAL);

    // 1. splits (inputs, weights) + zero row sums
    split3_k<<<dim3(2048, 1, 3), 256>>>(q, kx, vx, Xq, Xk, Xv, NTOK * DIN / 8);
    split3_k<<<dim3(512,  1, 3), 256>>>(Wq, Wk, Wv, Wqb, Wkb, Wvb, DM * DIN / 8);
    zero_k<<<(BN * SEQ + 1023) / 1024, 1024>>>(rs, BN * SEQ);

    // 2. Q and K projections (persistent, T=512)
    tc_gemm<0><<<NPERS, 256, SMEM_TOTAL>>>(
        Xq, Wqb, Xk, Wkb, bq, bk, nullptr, Qb, Kb, nullptr,
        512, DIN, 1.0f, 0, 0, 0);

    // 3. Vt = Wv * Xv^T (+bv) (persistent, T=256)
    tc_gemm<2><<<NPERS, 256, SMEM_TOTAL>>>(
        Wvb, Xv, nullptr, nullptr, bv, nullptr, nullptr, Vt, nullptr, nullptr,
        256, DIN, 1.0f, 0, 4194304u, 0);

    // 4. scores + exp + row sums -> fp16 P (persistent, T=512)
    tc_gemm<3><<<NPERS, 256, SMEM_TOTAL>>>(
        Qb, Kb, nullptr, nullptr, nullptr, nullptr, nullptr, Pb, nullptr, rs,
        512, DM, 0.03125f, 4194304u, 4194304u, 0);

    // 5. O = (P * Vt^T) / rowsum (persistent, T=256)
    tc_gemm<4><<<NPERS, 256, SMEM_TOTAL>>>(
        Pb, Vt, nullptr, nullptr, nullptr, nullptr, out, nullptr, nullptr, rs,
        256, SEQ, 1.0f, 8388608u, 4194304u, (size_t)SEQ * DM);
}

// round 14
// speedup vs baseline: 1.0515x; 1.0515x over previous
#include <cuda_runtime.h>
#include <cuda_bf16.h>
#include <cuda_fp16.h>
#include <cstdint>

// ---------------------------------------------------------------------------
// Problem constants
// ---------------------------------------------------------------------------
#define BN   8
#define SEQ  2048
#define DIN  1024
#define DM   1024
#define NTOK (BN*SEQ)          // 16384

// ---------------------------------------------------------------------------
// Blocked fp16 operand layout (round-9/12 validated):
//   operand[row, k] stored as 32KB blocks indexed [row/256][k/64].
//   Block: 256 rows x 128B; row = 64 fp16 k-values, SW128-swizzled.
//   GEMM chunk (K=64) load = TWO contiguous 32KB cp.async.bulk copies.
// NO clusters; NO persistence (rounds 10/11/13 falsified both).
// ---------------------------------------------------------------------------
#define SWZ128(off) ((off) ^ (((off) >> 3) & 0x70))

__device__ uint8_t g_Xq[(size_t)NTOK*DIN*2];
__device__ uint8_t g_Xk[(size_t)NTOK*DIN*2];
__device__ uint8_t g_Xv[(size_t)NTOK*DIN*2];
__device__ uint8_t g_Wq[(size_t)DM*DIN*2];
__device__ uint8_t g_Wk[(size_t)DM*DIN*2];
__device__ uint8_t g_Wv[(size_t)DM*DIN*2];
__device__ uint8_t g_Qb[(size_t)NTOK*DM*2];          // 4MB/batch, nkc=16
__device__ uint8_t g_Kb[(size_t)NTOK*DM*2];
__device__ uint8_t g_Vt[(size_t)BN*DM*SEQ*2];        // rows=v, k=s, nkc=32, 4MB/batch
__device__ uint8_t g_Pb[(size_t)BN*SEQ*SEQ*2];       // rows=q, k=s, nkc=32, 8MB/batch
__device__ float   g_rs[(size_t)BN*SEQ];

// ---------------------------------------------------------------------------
// Helpers available on base compute_103
// ---------------------------------------------------------------------------
__device__ __forceinline__ uint32_t smem_u32(const void* p) {
    uint32_t a;
    asm("{ .reg .u64 t; cvta.to.shared.u64 t, %1; cvt.u32.u64 %0, t; }"
        : "=r"(a) : "l"(p));
    return a;
}
__device__ __forceinline__ void cp16(uint32_t dst, const void* src) {
    asm volatile("cp.async.cg.shared.global [%0], [%1], 16;" :: "r"(dst), "l"(src));
}
#define CP_COMMIT()  asm volatile("cp.async.commit_group;" ::: "memory")
#define CP_WAIT(N)   asm volatile("cp.async.wait_group %0;" :: "n"(N) : "memory")

__device__ __forceinline__ void mma16816h(float* c, const uint32_t* a,
                                          uint32_t b0, uint32_t b1) {
    asm volatile(
        "mma.sync.aligned.m16n8k16.row.col.f32.f16.f16.f32 "
        "{%0,%1,%2,%3}, {%4,%5,%6,%7}, {%8,%9}, {%0,%1,%2,%3};"
        : "+f"(c[0]), "+f"(c[1]), "+f"(c[2]), "+f"(c[3])
        : "r"(a[0]), "r"(a[1]), "r"(a[2]), "r"(a[3]), "r"(b0), "r"(b1));
}

__device__ __forceinline__ uint32_t pkh2(__half a, __half b) {
    __half2 t; t.x = a; t.y = b;
    return *(uint32_t*)&t;
}
// scalar fp16 store into blocked layout (fallback path)
__device__ __forceinline__ void store_blk1(uint8_t* base, int row, int k,
                                           int nkc, float v) {
    const size_t blk = (((size_t)(row >> 8)) * nkc + (k >> 6)) << 15;
    const uint32_t off = (uint32_t)(row & 255) * 128 + (k & 63) * 2;
    *(__half*)(base + blk + SWZ128(off)) = __float2half(v);
}

// bulk copy (UBLKCP): contiguous gmem -> smem, completion via mbarrier tx-bytes
__device__ __forceinline__ void bulk_ld(uint32_t dst, const void* src,
                                        uint32_t bytes, uint32_t mbar) {
    asm volatile(
        "cp.async.bulk.shared::cluster.global.mbarrier::complete_tx::bytes "
        "[%0], [%1], %2, [%3];"
        :: "r"(dst), "l"(src), "r"(bytes), "r"(mbar) : "memory");
}
#define MBAR_INIT(addr, cnt) \
    asm volatile("mbarrier.init.shared.b64 [%0], %1;" :: "r"((uint32_t)(addr)), "r"((uint32_t)(cnt)) : "memory")
#define MBAR_EXPECT(addr, tx) \
    asm volatile("mbarrier.arrive.expect_tx.shared.b64 _, [%0], %1;" :: "r"((uint32_t)(addr)), "r"((uint32_t)(tx)) : "memory")
#define MBAR_WAIT(mbar, par) do { \
    uint32_t _m = (uint32_t)(mbar), _p = (uint32_t)(par), _d; \
    asm volatile("{\n\t.reg .pred p;\n\t" \
        "mbarrier.try_wait.parity.acquire.cta.shared::cta.b64 p, [%1], %2;\n\t" \
        "selp.b32 %0, 1, 0, p;\n\t}" : "=r"(_d) : "r"(_m), "r"(_p) : "memory"); \
    if (!_d) { \
        asm volatile("{\n\t.reg .pred P1;\n\t" \
            "WL_%=:\n\t" \
            "mbarrier.try_wait.parity.acquire.cta.shared::cta.b64 P1, [%0], %1, 0x989680;\n\t" \
            "@P1 bra.uni WD_%=;\n\tbra.uni WL_%=;\n\tWD_%=:\n\t}" \
            :: "r"(_m), "r"(_p) : "memory"); \
    } \
} while (0)

// ---------------------------------------------------------------------------
// tcgen05 helpers — ONLY compiled when the build has a compute_103a pass.
// ---------------------------------------------------------------------------
#if defined(__CUDA_ARCH_FEAT_SM103_ALL)
__device__ __forceinline__ uint32_t elect_one_pred() {
    uint32_t pred;
    asm volatile(
        "{\n\t.reg .pred p;\n\t"
        "elect.sync _|p, 0xFFFFFFFF;\n\t"
        "selp.b32 %0, 1, 0, p;\n\t}"
        : "=r"(pred));
    return pred;
}
#define TCGEN05_ALLOC(a, n) \
    asm volatile("tcgen05.alloc.cta_group::1.sync.aligned.shared::cta.b32 [%0], %1;" \
        :: "r"((uint32_t)(a)), "r"((uint32_t)(n)) : "memory")
#define TCGEN05_RELINQUISH() \
    asm volatile("tcgen05.relinquish_alloc_permit.cta_group::1.sync.aligned;")
#define TCGEN05_DEALLOC(t, n) \
    asm volatile("tcgen05.dealloc.cta_group::1.sync.aligned.b32 %0, %1;" :: "r"(t), "r"((uint32_t)(n)))
#define TCGEN05_COMMIT(m) \
    asm volatile("tcgen05.commit.cta_group::1.mbarrier::arrive::one.shared::cluster.b64 [%0];" \
        :: "r"((uint32_t)(m)) : "memory")
#define TCGEN05_WAIT_LD()    asm volatile("tcgen05.wait::ld.sync.aligned;" ::: "memory")
#define TCGEN05_FENCE_AFTER() asm volatile("tcgen05.fence::after_thread_sync;" ::: "memory")
#define TCGEN05_LD_32X32B_X32(r, ta) \
    asm volatile( \
        "tcgen05.ld.sync.aligned.32x32b.x32.b32 " \
        "{%0, %1, %2, %3, %4, %5, %6, %7, " \
        " %8, %9, %10, %11, %12, %13, %14, %15, " \
        " %16, %17, %18, %19, %20, %21, %22, %23, " \
        " %24, %25, %26, %27, %28, %29, %30, %31}, [%32];" \
        : "=r"((r)[0]),  "=r"((r)[1]),  "=r"((r)[2]),  "=r"((r)[3]), \
          "=r"((r)[4]),  "=r"((r)[5]),  "=r"((r)[6]),  "=r"((r)[7]), \
          "=r"((r)[8]),  "=r"((r)[9]),  "=r"((r)[10]), "=r"((r)[11]), \
          "=r"((r)[12]), "=r"((r)[13]), "=r"((r)[14]), "=r"((r)[15]), \
          "=r"((r)[16]), "=r"((r)[17]), "=r"((r)[18]), "=r"((r)[19]), \
          "=r"((r)[20]), "=r"((r)[21]), "=r"((r)[22]), "=r"((r)[23]), \
          "=r"((r)[24]), "=r"((r)[25]), "=r"((r)[26]), "=r"((r)[27]), \
          "=r"((r)[28]), "=r"((r)[29]), "=r"((r)[30]), "=r"((r)[31]) \
        : "r"(ta))
static constexpr uint64_t SMEM_DESC_BASE_SW128 =
    (uint64_t(2)  << 61) | (uint64_t(1) << 46) | (uint64_t(64) << 32) | (uint64_t(1) << 16);
#define MAKE_SMEM_DESC(ba) (SMEM_DESC_BASE_SW128 | ((uint64_t)((ba) >> 4) & 0x3FFF))
__device__ __forceinline__ void mma_f16_ss(uint32_t d, uint64_t ad, uint64_t bd,
                                           uint32_t idesc, bool acc) {
    uint32_t en = acc ? 1u : 0u;
    asm volatile(
        "{\n\t.reg .pred p;\n\t"
        "setp.ne.u32 p, %5, 0;\n\t"
        "tcgen05.mma.cta_group::1.kind::f16 [%0], %1, %2, %3, {%4, %4, %4, %4}, p;\n\t"
        "}"
        :: "r"(d), "l"(ad), "l"(bd), "r"(idesc), "r"(0u), "r"(en)
        : "memory");
}
#endif  // __CUDA_ARCH_FEAT_SM103_ALL

// ---------------------------------------------------------------------------
// GEMM: C[M,N] = A[M,K] * B[N,K]^T, single-pass fp16 operands (blocked).
// tcgen05: CTA 256x256, TK=64, two M=128 TMEM accumulators, 3-stage pipeline,
// 2x32KB bulk loads/chunk, single-elected-thread mainloop, deferred MMA wait.
// Epilogue: paired LDTM.x32 (one wait per 64 columns).
// MODE 0: dual projection (z selects {Xq,Wq,bq,Qb}/{Xk,Wk,bk,Kb}), bias[n], nkc=16
// MODE 2: Vt = Wv * Xv^T (+bias[m]); out rows=v, k=s, nkc=32
// MODE 3: e=expf(acc*alpha) f16 out + row-sum atomics [scores->P], nkc=32
// MODE 4: f32 out = acc / rowsum[m]  [PV]
// ---------------------------------------------------------------------------
constexpr int OFF_B  = 32768;
constexpr int STAGE  = 65536;                     // 32KB A + 32KB B
constexpr int SMEM_DATA = 1024;
constexpr int SMEM_TOTAL = SMEM_DATA + 3 * STAGE; // 197632

template <int MODE>
__global__ void __launch_bounds__(256, 1) tc_gemm(
    const uint8_t* __restrict__ Ab, const uint8_t* __restrict__ Bb,
    const uint8_t* __restrict__ A2b, const uint8_t* __restrict__ B2b,
    const float* __restrict__ bias, const float* __restrict__ bias2,
    float* __restrict__ Cf, uint8_t* __restrict__ Cb, uint8_t* __restrict__ C2b,
    float* __restrict__ rs,
    int K, float alpha,
    size_t sAb, size_t sBb, size_t sC)
{
    extern __shared__ char smem[];
    const int tid   = threadIdx.x;
    const size_t zb = blockIdx.z;
    const int m0    = blockIdx.y * 256;
    const int n0    = blockIdx.x * 256;
    const int NC    = K >> 6;                 // 64-k chunks

    if (MODE == 0 && zb == 1) {
        Ab = A2b; Bb = B2b; Cb = C2b; bias = bias2;
    }
    Ab += zb * sAb;  Bb += zb * sBb;
    const size_t blkA0 = ((size_t)(m0 >> 8)) * NC;
    const size_t blkB0 = ((size_t)(n0 >> 8)) * NC;

#if defined(__CUDA_ARCH_FEAT_SM103_ALL)
    // ======================= tcgen05 path (sm_103a) ========================
    const uint32_t sb = smem_u32(smem);

    if (tid < 32) TCGEN05_ALLOC(sb + 0, 512);
    if (tid >= 32 && tid < 64) TCGEN05_RELINQUISH();
    if (tid == 0) {
#pragma unroll
        for (int s = 0; s < 3; ++s) {
            MBAR_INIT(sb + 8  + 8 * s, 1);   // full (tx-based)
            MBAR_INIT(sb + 32 + 8 * s, 1);   // mma done
        }
    }
    __syncthreads();
    uint32_t tmem;
    asm volatile("ld.shared.b32 %0, [%1];" : "=r"(tmem) : "r"(sb + 0));

    // kind::f16, atype=btype=F16 (0), dtype F32, N=256, M=128 per dispatch
    constexpr uint32_t IDESC =
        (1u << 4) | ((256 / 8) << 17) | ((128 / 16) << 24);

    if (tid < 32 && elect_one_pred()) {
        auto load_chunk = [&](int kc, int st) {
            const uint32_t full = sb + 8 + 8 * st;
            const uint32_t base = sb + SMEM_DATA + st * STAGE;
            MBAR_EXPECT(full, STAGE);
            bulk_ld(base,         Ab + ((blkA0 + kc) << 15), 32768, full);
            bulk_ld(base + OFF_B, Bb + ((blkB0 + kc) << 15), 32768, full);
        };

        load_chunk(0, 0);
        if (NC > 1) load_chunk(1, 1);
        if (NC > 2) load_chunk(2, 2);

        int fph[3] = {0, 0, 0}, mph[3] = {0, 0, 0};
        for (int c = 0; c < NC; ++c) {
            const int st = c % 3;
            MBAR_WAIT(sb + 8 + 8 * st, fph[st]);
            fph[st] ^= 1;

            const uint32_t base = sb + SMEM_DATA + st * STAGE;
            const uint64_t daA0 = MAKE_SMEM_DESC(base);
            const uint64_t daA1 = MAKE_SMEM_DESC(base + 16384);
            const uint64_t db   = MAKE_SMEM_DESC(base + OFF_B);
#pragma unroll
            for (int half = 0; half < 2; ++half) {
                const uint64_t da = half ? daA1 : daA0;
                const uint32_t dt = tmem + half * 256;
#pragma unroll
                for (int ks = 0; ks < 4; ++ks)   // 16 fp16 per step = +2 units
                    mma_f16_ss(dt, da + ks * 2, db + ks * 2, IDESC,
                               !(c == 0 && ks == 0));
            }
            TCGEN05_COMMIT(sb + 32 + 8 * st);

            if (c > 0) {
                const int sp = (c - 1) % 3;
                MBAR_WAIT(sb + 32 + 8 * sp, mph[sp]);
                mph[sp] ^= 1;
                if (c + 2 < NC) load_chunk(c + 2, sp);
            }
        }
        MBAR_WAIT(sb + 32 + 8 * ((NC - 1) % 3), mph[(NC - 1) % 3]);
    }
    __syncthreads();
    TCGEN05_FENCE_AFTER();

    // epilogue: warps 0-3 -> D0 (rows 0-127), warps 4-7 -> D1 (rows 128-255)
    // paired x32 loads: one tcgen05.wait per 64 columns (aligned to 32KB block)
    {
        const int half = tid >> 7;
        const int w4   = (tid >> 5) & 3;
        const int lid  = tid & 31;
        const int m    = m0 + half * 128 + w4 * 32 + lid;
        const uint32_t dt = tmem + half * 256;
        float inv = 1.0f, lsum = 0.0f, bm = 0.0f;
        if (MODE == 4) inv = 1.0f / rs[zb * SEQ + m];
        if (MODE == 2) bm  = bias[m];
        for (int j0 = 0; j0 < 256; j0 += 64) {
            uint32_t r[64];
            TCGEN05_LD_32X32B_X32(r,      dt + j0);
            TCGEN05_LD_32X32B_X32(r + 32, dt + j0 + 32);
            TCGEN05_WAIT_LD();
            if (MODE == 4) {
                float4* dst = (float4*)(Cf + zb * sC + (size_t)m * DM + n0 + j0);
#pragma unroll
                for (int i = 0; i < 16; ++i) {
                    float4 v;
                    v.x = __uint_as_float(r[4 * i + 0]) * inv;
                    v.y = __uint_as_float(r[4 * i + 1]) * inv;
                    v.z = __uint_as_float(r[4 * i + 2]) * inv;
                    v.w = __uint_as_float(r[4 * i + 3]) * inv;
                    dst[i] = v;
                }
            } else {   // MODE 0 / 2 / 3: blocked fp16 store (64 vals = 128B row)
                uint32_t H[32];
#pragma unroll
                for (int i = 0; i < 64; i += 2) {
                    float v0, v1;
                    if (MODE == 3) {
                        v0 = __expf(__uint_as_float(r[i])     * alpha);
                        v1 = __expf(__uint_as_float(r[i + 1]) * alpha);
                        lsum += v0 + v1;
                    } else if (MODE == 0) {
                        v0 = __uint_as_float(r[i])     + bias[n0 + j0 + i];
                        v1 = __uint_as_float(r[i + 1]) + bias[n0 + j0 + i + 1];
                    } else {
                        v0 = __uint_as_float(r[i])     + bm;
                        v1 = __uint_as_float(r[i + 1]) + bm;
                    }
                    H[i >> 1] = pkh2(__float2half(v0), __float2half(v1));
                }
                uint8_t* base;
                size_t blk;
                const int row = m & 255;
                if (MODE == 0) {          // Q/K: 4MB/batch(by m), nkc = 16
                    base = Cb + (size_t)(m >> 11) * 4194304u;
                    blk  = ((((size_t)((m & 2047) >> 8)) * 16) + ((n0 + j0) >> 6)) << 15;
                } else if (MODE == 3) {   // P: 8MB/batch, nkc = 32
                    base = Cb + zb * 8388608u;
                    blk  = ((((size_t)(m >> 8)) * 32) + ((n0 + j0) >> 6)) << 15;
                } else {                  // Vt: 4MB/batch, nkc = 32
                    base = Cb + zb * 4194304u;
                    blk  = ((((size_t)(m >> 8)) * 32) + ((n0 + j0) >> 6)) << 15;
                }
#pragma unroll
                for (int q = 0; q < 8; ++q) {
                    uint4 hv;
                    hv.x = H[4*q]; hv.y = H[4*q+1]; hv.z = H[4*q+2]; hv.w = H[4*q+3];
                    *(uint4*)(base + blk +
                              SWZ128((uint32_t)row * 128 + q * 16)) = hv;
                }
            }
        }
        if (MODE == 3) atomicAdd(&rs[zb * SEQ + m], lsum);
    }
    __syncthreads();
    if (tid < 32) TCGEN05_DEALLOC(tmem, 512);

#elif defined(__CUDA_ARCH__)
    // ================= mma.sync fallback (base compute_103) =================
    // Correctness insurance only (sm_103a cubin is the one that runs).
    constexpr int STR = 20;                 // words per 32-fp16 sub-row (padded)
    constexpr int TILE_W = 128 * STR;
    constexpr int STAGE_W = 2 * TILE_W;     // A tile + B tile
    const uint32_t sbase = smem_u32(smem);
    const int lane = tid & 31, wid = tid >> 5;
    const int wm = wid >> 1, wn = wid & 1;
    const int g = lane >> 2, tg = lane & 3;
    const int NC32 = K >> 5;

    auto load_chunk = [&](int c32, int st, int mbase, int nbase) {
        const int q = tid & 3, r0 = tid >> 2;
        const uint32_t dst0 = sbase + st * STAGE_W * 4;
        const int kc = c32 >> 1, h = c32 & 1;
#pragma unroll
        for (int i = 0; i < 2; ++i) {
            const int ra = mbase + r0 + 64 * i;
            const int rb = nbase + r0 + 64 * i;
            const uint32_t ro = (uint32_t)((r0 + 64 * i) * STR + q * 4) * 4;
            const size_t ba = (((size_t)(ra >> 8)) * NC + kc) << 15;
            const size_t bb = (((size_t)(rb >> 8)) * NC + kc) << 15;
            const uint32_t oa = (uint32_t)(ra & 255) * 128 + h * 64 + q * 16;
            const uint32_t ob = (uint32_t)(rb & 255) * 128 + h * 64 + q * 16;
            cp16(dst0 + ro,                Ab + ba + SWZ128(oa));
            cp16(dst0 + TILE_W * 4 + ro,   Bb + bb + SWZ128(ob));
        }
    };

    for (int mh = 0; mh < 2; ++mh) {
        const int mb0 = m0 + mh * 128;
        for (int np = 0; np < 2; ++np) {
            const int nb0 = n0 + np * 128;

            float acc[2][8][4];
#pragma unroll
            for (int a = 0; a < 2; ++a)
#pragma unroll
                for (int b = 0; b < 8; ++b)
#pragma unroll
                    for (int c = 0; c < 4; ++c) acc[a][b][c] = 0.0f;

            load_chunk(0, 0, mb0, nb0); CP_COMMIT();

            for (int c = 0; c < NC32; ++c) {
                const int st = c & 1;
                if (c + 1 < NC32) { load_chunk(c + 1, st ^ 1, mb0, nb0); CP_COMMIT(); CP_WAIT(1); }
                else              { CP_WAIT(0); }
                __syncthreads();

                const uint32_t* s0 = (const uint32_t*)smem + st * STAGE_W;
#pragma unroll
                for (int ks = 0; ks < 2; ++ks) {
                    uint32_t af[2][4];
#pragma unroll
                    for (int mt = 0; mt < 2; ++mt) {
                        const int rb = wm * 32 + mt * 16;
                        const uint32_t* pa = s0 + (rb + g) * STR + ks * 8 + tg;
                        af[mt][0] = pa[0];           af[mt][2] = pa[4];
                        af[mt][1] = pa[8 * STR];     af[mt][3] = pa[8 * STR + 4];
                    }
#pragma unroll
                    for (int nt = 0; nt < 8; ++nt) {
                        const int nb = wn * 64 + nt * 8;
                        const uint32_t* pb = s0 + TILE_W + (nb + g) * STR + ks * 8 + tg;
                        const uint32_t b0 = pb[0], b1 = pb[4];
#pragma unroll
                        for (int mt = 0; mt < 2; ++mt)
                            mma16816h(acc[mt][nt], af[mt], b0, b1);
                    }
                }
                __syncthreads();
            }

#pragma unroll
            for (int mt = 0; mt < 2; ++mt) {
#pragma unroll
                for (int nt = 0; nt < 8; ++nt) {
                    const int m1 = mb0 + wm * 32 + mt * 16 + g;
                    const int m2 = m1 + 8;
                    const int n  = nb0 + wn * 64 + nt * 8 + tg * 2;
                    const float* a = acc[mt][nt];
                    if (MODE == 4) {
                        const float i1 = 1.0f / rs[zb * SEQ + m1];
                        const float i2 = 1.0f / rs[zb * SEQ + m2];
                        float2 v0; v0.x = a[0] * i1; v0.y = a[1] * i1;
                        float2 v1; v1.x = a[2] * i2; v1.y = a[3] * i2;
                        *(float2*)(Cf + zb * sC + (size_t)m1 * DM + n) = v0;
                        *(float2*)(Cf + zb * sC + (size_t)m2 * DM + n) = v1;
                    } else if (MODE == 0) {
#pragma unroll
                        for (int e = 0; e < 4; ++e) {
                            const int m = (e < 2) ? m1 : m2;
                            const int nn = n + (e & 1);
                            store_blk1(Cb + (size_t)(m >> 11) * 4194304u,
                                       m & 2047, nn, 16, a[e] + bias[nn]);
                        }
                    } else if (MODE == 3) {
                        float e0 = __expf(a[0] * alpha), e1 = __expf(a[1] * alpha);
                        float e2 = __expf(a[2] * alpha), e3 = __expf(a[3] * alpha);
                        atomicAdd(&rs[zb * SEQ + m1], e0 + e1);
                        atomicAdd(&rs[zb * SEQ + m2], e2 + e3);
                        uint8_t* base = Cb + zb * 8388608u;
                        store_blk1(base, m1, n,     32, e0);
                        store_blk1(base, m1, n + 1, 32, e1);
                        store_blk1(base, m2, n,     32, e2);
                        store_blk1(base, m2, n + 1, 32, e3);
                    } else {  // MODE 2
                        uint8_t* base = Cb + zb * 4194304u;
#pragma unroll
                        for (int e = 0; e < 4; ++e) {
                            const int m = (e < 2) ? m1 : m2;
                            const int nn = n + (e & 1);
                            store_blk1(base, m, nn, 32, a[e] + bias[m]);
                        }
                    }
                }
            }
            __syncthreads();
        }
    }
#endif
}

// ---------------------------------------------------------------------------
// f32 -> blocked fp16 (K fixed = 1024; nkc = 16). z selects among 3 tensors.
// v2: 4 units per iteration, 8 independent 16B loads front-loaded (MLP=8).
// ---------------------------------------------------------------------------
__global__ void __launch_bounds__(256) split3_k(
    const float* __restrict__ x0, const float* __restrict__ x1,
    const float* __restrict__ x2,
    uint8_t* __restrict__ d0, uint8_t* __restrict__ d1,
    uint8_t* __restrict__ d2, int nunits)
{
    const int z = blockIdx.z;
    const float* x = (z == 0) ? x0 : (z == 1) ? x1 : x2;
    uint8_t*   dst = (z == 0) ? d0 : (z == 1) ? d1 : d2;
    const int stride = (int)gridDim.x * 256;
    int u0 = blockIdx.x * 256 + threadIdx.x;

    // main loop: 4 units (128B) per iteration, loads batched for MLP
    for (; u0 + 3 * stride < nunits; u0 += 4 * stride) {
        float4 f[8];
#pragma unroll
        for (int k = 0; k < 4; ++k) {
            const int u = u0 + k * stride;
            const int r = u >> 7, j = u & 127;
            const float* p = x + ((size_t)r << 10) + (j << 3);
            f[2 * k]     = *(const float4*)p;
            f[2 * k + 1] = *(const float4*)(p + 4);
        }
#pragma unroll
        for (int k = 0; k < 4; ++k) {
            const int u = u0 + k * stride;
            const int r = u >> 7, j = u & 127;
            uint4 hv;
            hv.x = pkh2(__float2half(f[2*k].x),   __float2half(f[2*k].y));
            hv.y = pkh2(__float2half(f[2*k].z),   __float2half(f[2*k].w));
            hv.z = pkh2(__float2half(f[2*k+1].x), __float2half(f[2*k+1].y));
            hv.w = pkh2(__float2half(f[2*k+1].z), __float2half(f[2*k+1].w));
            const size_t blk = ((((size_t)(r >> 8)) << 4) + (j >> 3)) << 15;
            const uint32_t ro = (uint32_t)(r & 255) * 128 + (j & 7) * 16;
            *(uint4*)(dst + blk + SWZ128(ro)) = hv;
        }
    }
    // tail
    for (; u0 < nunits; u0 += stride) {
        const int r = u0 >> 7, j = u0 & 127;
        const float4 f0 = *(const float4*)(x + ((size_t)r << 10) + (j << 3));
        const float4 f1 = *(const float4*)(x + ((size_t)r << 10) + (j << 3) + 4);
        uint4 hv;
        hv.x = pkh2(__float2half(f0.x), __float2half(f0.y));
        hv.y = pkh2(__float2half(f0.z), __float2half(f0.w));
        hv.z = pkh2(__float2half(f1.x), __float2half(f1.y));
        hv.w = pkh2(__float2half(f1.z), __float2half(f1.w));
        const size_t blk = ((((size_t)(r >> 8)) << 4) + (j >> 3)) << 15;
        const uint32_t ro = (uint32_t)(r & 255) * 128 + (j & 7) * 16;
        *(uint4*)(dst + blk + SWZ128(ro)) = hv;
    }
}

__global__ void __launch_bounds__(1024) zero_k(float* __restrict__ p, int n)
{
    int i = blockIdx.x * 1024 + threadIdx.x;
    if (i < n) p[i] = 0.0f;
}

// ---------------------------------------------------------------------------
extern "C" void kernel_launch(void* const* d_in, const int* in_sizes, int n_in,
                              void* d_out, int out_size)
{
    (void)in_sizes; (void)n_in; (void)out_size;
    const float* q  = (const float*)d_in[0];
    const float* kx = (const float*)d_in[1];
    const float* vx = (const float*)d_in[2];
    const float* Wq = (const float*)d_in[3];
    const float* bq = (const float*)d_in[4];
    const float* Wk = (const float*)d_in[5];
    const float* bk = (const float*)d_in[6];
    const float* Wv = (const float*)d_in[7];
    const float* bv = (const float*)d_in[8];
    float* out = (float*)d_out;

    uint8_t *Xq, *Xk, *Xv, *Wqb, *Wkb, *Wvb, *Qb, *Kb, *Vt, *Pb;
    float* rs;
    cudaGetSymbolAddress((void**)&Xq,  g_Xq);  cudaGetSymbolAddress((void**)&Xk,  g_Xk);
    cudaGetSymbolAddress((void**)&Xv,  g_Xv);
    cudaGetSymbolAddress((void**)&Wqb, g_Wq);  cudaGetSymbolAddress((void**)&Wkb, g_Wk);
    cudaGetSymbolAddress((void**)&Wvb, g_Wv);
    cudaGetSymbolAddress((void**)&Qb,  g_Qb);  cudaGetSymbolAddress((void**)&Kb,  g_Kb);
    cudaGetSymbolAddress((void**)&Vt,  g_Vt);  cudaGetSymbolAddress((void**)&Pb,  g_Pb);
    cudaGetSymbolAddress((void**)&rs,  g_rs);

    cudaFuncSetAttribute(tc_gemm<0>, cudaFuncAttributeMaxDynamicSharedMemorySize, SMEM_TOTAL);
    cudaFuncSetAttribute(tc_gemm<2>, cudaFuncAttributeMaxDynamicSharedMemorySize, SMEM_TOTAL);
    cudaFuncSetAttribute(tc_gemm<3>, cudaFuncAttributeMaxDynamicSharedMemorySize, SMEM_TOTAL);
    cudaFuncSetAttribute(tc_gemm<4>, cudaFuncAttributeMaxDynamicSharedMemorySize, SMEM_TOTAL);

    // 1. splits (inputs: 4 units/thread; weights: 4 units/thread) + zero rs
    split3_k<<<dim3(512, 1, 3), 256>>>(q, kx, vx, Xq, Xk, Xv, NTOK * DIN / 8);
    split3_k<<<dim3(128, 1, 3), 256>>>(Wq, Wk, Wv, Wqb, Wkb, Wvb, DM * DIN / 8);
    zero_k<<<(BN * SEQ + 1023) / 1024, 1024>>>(rs, BN * SEQ);

    // 2. Q and K projections in ONE launch (z selects operand set)
    tc_gemm<0><<<dim3(DM / 256, NTOK / 256, 2), 256, SMEM_TOTAL>>>(
        Xq, Wqb, Xk, Wkb, bq, bk, nullptr, Qb, Kb, nullptr,
        DIN, 1.0f, 0, 0, 0);

    // 3. Vt = Wv * Xv^T (+bv)
    tc_gemm<2><<<dim3(SEQ / 256, DM / 256, BN), 256, SMEM_TOTAL>>>(
        Wvb, Xv, nullptr, nullptr, bv, nullptr, nullptr, Vt, nullptr, nullptr,
        DIN, 1.0f, 0, 4194304u, 0);

    // 4. scores + exp + row sums -> fp16 P
    tc_gemm<3><<<dim3(SEQ / 256, SEQ / 256, BN), 256, SMEM_TOTAL>>>(
        Qb, Kb, nullptr, nullptr, nullptr, nullptr, nullptr, Pb, nullptr, rs,
        DM, 0.03125f, 4194304u, 4194304u, 0);

    // 5. O = (P * Vt^T) / rowsum
    tc_gemm<4><<<dim3(DM / 256, SEQ / 256, BN), 256, SMEM_TOTAL>>>(
        Pb, Vt, nullptr, nullptr, nullptr, nullptr, out, nullptr, nullptr, rs,
        SEQ, 1.0f, 8388608u, 4194304u, (size_t)SEQ * DM);
}

// round 15
// speedup vs baseline: 1.0604x; 1.0085x over previous
#include <cuda_runtime.h>
#include <cuda_bf16.h>
#include <cuda_fp16.h>
#include <cstdint>

// ---------------------------------------------------------------------------
// Problem constants
// ---------------------------------------------------------------------------
#define BN   8
#define SEQ  2048
#define DIN  1024
#define DM   1024
#define NTOK (BN*SEQ)          // 16384

// ---------------------------------------------------------------------------
// Blocked fp16 operand layout (round-9/12 validated):
//   operand[row, k] stored as 32KB blocks indexed [row/256][k/64].
//   Block: 256 rows x 128B; row = 64 fp16 k-values, SW128-swizzled.
//   GEMM chunk (K=64) load = TWO contiguous 32KB cp.async.bulk copies.
// Round-15: Q/K projections + Vt projection MERGED into ONE 768-CTA launch
//   (independent tiles, same K=1024 mainloop) to kill the launch boundary.
// NO clusters; NO persistence (falsified in rounds 10/11/13).
// ---------------------------------------------------------------------------
#define SWZ128(off) ((off) ^ (((off) >> 3) & 0x70))

__device__ uint8_t g_Xq[(size_t)NTOK*DIN*2];
__device__ uint8_t g_Xk[(size_t)NTOK*DIN*2];
__device__ uint8_t g_Xv[(size_t)NTOK*DIN*2];
__device__ uint8_t g_Wq[(size_t)DM*DIN*2];
__device__ uint8_t g_Wk[(size_t)DM*DIN*2];
__device__ uint8_t g_Wv[(size_t)DM*DIN*2];
__device__ uint8_t g_Qb[(size_t)NTOK*DM*2];          // 4MB/batch, nkc=16
__device__ uint8_t g_Kb[(size_t)NTOK*DM*2];
__device__ uint8_t g_Vt[(size_t)BN*DM*SEQ*2];        // rows=v, k=s, nkc=32, 4MB/batch
__device__ uint8_t g_Pb[(size_t)BN*SEQ*SEQ*2];       // rows=q, k=s, nkc=32, 8MB/batch
__device__ float   g_rs[(size_t)BN*SEQ];

// ---------------------------------------------------------------------------
// Helpers available on base compute_103
// ---------------------------------------------------------------------------
__device__ __forceinline__ uint32_t smem_u32(const void* p) {
    uint32_t a;
    asm("{ .reg .u64 t; cvta.to.shared.u64 t, %1; cvt.u32.u64 %0, t; }"
        : "=r"(a) : "l"(p));
    return a;
}
__device__ __forceinline__ void cp16(uint32_t dst, const void* src) {
    asm volatile("cp.async.cg.shared.global [%0], [%1], 16;" :: "r"(dst), "l"(src));
}
#define CP_COMMIT()  asm volatile("cp.async.commit_group;" ::: "memory")
#define CP_WAIT(N)   asm volatile("cp.async.wait_group %0;" :: "n"(N) : "memory")

__device__ __forceinline__ void mma16816h(float* c, const uint32_t* a,
                                          uint32_t b0, uint32_t b1) {
    asm volatile(
        "mma.sync.aligned.m16n8k16.row.col.f32.f16.f16.f32 "
        "{%0,%1,%2,%3}, {%4,%5,%6,%7}, {%8,%9}, {%0,%1,%2,%3};"
        : "+f"(c[0]), "+f"(c[1]), "+f"(c[2]), "+f"(c[3])
        : "r"(a[0]), "r"(a[1]), "r"(a[2]), "r"(a[3]), "r"(b0), "r"(b1));
}

__device__ __forceinline__ uint32_t pkh2(__half a, __half b) {
    __half2 t; t.x = a; t.y = b;
    return *(uint32_t*)&t;
}
// scalar fp16 store into blocked layout (fallback path)
__device__ __forceinline__ void store_blk1(uint8_t* base, int row, int k,
                                           int nkc, float v) {
    const size_t blk = (((size_t)(row >> 8)) * nkc + (k >> 6)) << 15;
    const uint32_t off = (uint32_t)(row & 255) * 128 + (k & 63) * 2;
    *(__half*)(base + blk + SWZ128(off)) = __float2half(v);
}

// bulk copy (UBLKCP): contiguous gmem -> smem, completion via mbarrier tx-bytes
__device__ __forceinline__ void bulk_ld(uint32_t dst, const void* src,
                                        uint32_t bytes, uint32_t mbar) {
    asm volatile(
        "cp.async.bulk.shared::cluster.global.mbarrier::complete_tx::bytes "
        "[%0], [%1], %2, [%3];"
        :: "r"(dst), "l"(src), "r"(bytes), "r"(mbar) : "memory");
}
#define MBAR_INIT(addr, cnt) \
    asm volatile("mbarrier.init.shared.b64 [%0], %1;" :: "r"((uint32_t)(addr)), "r"((uint32_t)(cnt)) : "memory")
#define MBAR_EXPECT(addr, tx) \
    asm volatile("mbarrier.arrive.expect_tx.shared.b64 _, [%0], %1;" :: "r"((uint32_t)(addr)), "r"((uint32_t)(tx)) : "memory")
#define MBAR_WAIT(mbar, par) do { \
    uint32_t _m = (uint32_t)(mbar), _p = (uint32_t)(par), _d; \
    asm volatile("{\n\t.reg .pred p;\n\t" \
        "mbarrier.try_wait.parity.acquire.cta.shared::cta.b64 p, [%1], %2;\n\t" \
        "selp.b32 %0, 1, 0, p;\n\t}" : "=r"(_d) : "r"(_m), "r"(_p) : "memory"); \
    if (!_d) { \
        asm volatile("{\n\t.reg .pred P1;\n\t" \
            "WL_%=:\n\t" \
            "mbarrier.try_wait.parity.acquire.cta.shared::cta.b64 P1, [%0], %1, 0x989680;\n\t" \
            "@P1 bra.uni WD_%=;\n\tbra.uni WL_%=;\n\tWD_%=:\n\t}" \
            :: "r"(_m), "r"(_p) : "memory"); \
    } \
} while (0)

// ---------------------------------------------------------------------------
// tcgen05 helpers — ONLY compiled when the build has a compute_103a pass.
// ---------------------------------------------------------------------------
#if defined(__CUDA_ARCH_FEAT_SM103_ALL)
__device__ __forceinline__ uint32_t elect_one_pred() {
    uint32_t pred;
    asm volatile(
        "{\n\t.reg .pred p;\n\t"
        "elect.sync _|p, 0xFFFFFFFF;\n\t"
        "selp.b32 %0, 1, 0, p;\n\t}"
        : "=r"(pred));
    return pred;
}
#define TCGEN05_ALLOC(a, n) \
    asm volatile("tcgen05.alloc.cta_group::1.sync.aligned.shared::cta.b32 [%0], %1;" \
        :: "r"((uint32_t)(a)), "r"((uint32_t)(n)) : "memory")
#define TCGEN05_RELINQUISH() \
    asm volatile("tcgen05.relinquish_alloc_permit.cta_group::1.sync.aligned;")
#define TCGEN05_DEALLOC(t, n) \
    asm volatile("tcgen05.dealloc.cta_group::1.sync.aligned.b32 %0, %1;" :: "r"(t), "r"((uint32_t)(n)))
#define TCGEN05_COMMIT(m) \
    asm volatile("tcgen05.commit.cta_group::1.mbarrier::arrive::one.shared::cluster.b64 [%0];" \
        :: "r"((uint32_t)(m)) : "memory")
#define TCGEN05_WAIT_LD()    asm volatile("tcgen05.wait::ld.sync.aligned;" ::: "memory")
#define TCGEN05_FENCE_AFTER() asm volatile("tcgen05.fence::after_thread_sync;" ::: "memory")
#define TCGEN05_LD_32X32B_X32(r, ta) \
    asm volatile( \
        "tcgen05.ld.sync.aligned.32x32b.x32.b32 " \
        "{%0, %1, %2, %3, %4, %5, %6, %7, " \
        " %8, %9, %10, %11, %12, %13, %14, %15, " \
        " %16, %17, %18, %19, %20, %21, %22, %23, " \
        " %24, %25, %26, %27, %28, %29, %30, %31}, [%32];" \
        : "=r"((r)[0]),  "=r"((r)[1]),  "=r"((r)[2]),  "=r"((r)[3]), \
          "=r"((r)[4]),  "=r"((r)[5]),  "=r"((r)[6]),  "=r"((r)[7]), \
          "=r"((r)[8]),  "=r"((r)[9]),  "=r"((r)[10]), "=r"((r)[11]), \
          "=r"((r)[12]), "=r"((r)[13]), "=r"((r)[14]), "=r"((r)[15]), \
          "=r"((r)[16]), "=r"((r)[17]), "=r"((r)[18]), "=r"((r)[19]), \
          "=r"((r)[20]), "=r"((r)[21]), "=r"((r)[22]), "=r"((r)[23]), \
          "=r"((r)[24]), "=r"((r)[25]), "=r"((r)[26]), "=r"((r)[27]), \
          "=r"((r)[28]), "=r"((r)[29]), "=r"((r)[30]), "=r"((r)[31]) \
        : "r"(ta))
static constexpr uint64_t SMEM_DESC_BASE_SW128 =
    (uint64_t(2)  << 61) | (uint64_t(1) << 46) | (uint64_t(64) << 32) | (uint64_t(1) << 16);
#define MAKE_SMEM_DESC(ba) (SMEM_DESC_BASE_SW128 | ((uint64_t)((ba) >> 4) & 0x3FFF))
__device__ __forceinline__ void mma_f16_ss(uint32_t d, uint64_t ad, uint64_t bd,
                                           uint32_t idesc, bool acc) {
    uint32_t en = acc ? 1u : 0u;
    asm volatile(
        "{\n\t.reg .pred p;\n\t"
        "setp.ne.u32 p, %5, 0;\n\t"
        "tcgen05.mma.cta_group::1.kind::f16 [%0], %1, %2, %3, {%4, %4, %4, %4}, p;\n\t"
        "}"
        :: "r"(d), "l"(ad), "l"(bd), "r"(idesc), "r"(0u), "r"(en)
        : "memory");
}
#endif  // __CUDA_ARCH_FEAT_SM103_ALL

// ---------------------------------------------------------------------------
// GEMM: C[M,N] = A[M,K] * B[N,K]^T, single-pass fp16 operands (blocked).
// tcgen05: CTA 256x256, TK=64, two M=128 TMEM accumulators, 3-stage pipeline,
// 2x32KB bulk loads/chunk, single-elected-thread mainloop, deferred MMA wait.
// Epilogue: paired LDTM.x32 (one wait per 64 columns).
// MODE 1: MERGED projections, 1-D grid of 768 tiles:
//   t<512  : Q/K proj (cls=t>>8): A=X?, B=W?, bias[n], out blocked nkc=16
//   t>=512 : Vt tile: A=Wv, B=Xv(batch), bias[m], out Vt nkc=32 (4MB/batch)
// MODE 3: e=expf(acc*alpha) f16 out + row-sum atomics [scores->P], nkc=32
// MODE 4: f32 out = acc / rowsum[m]  [PV]
// ---------------------------------------------------------------------------
constexpr int OFF_B  = 32768;
constexpr int STAGE  = 65536;                     // 32KB A + 32KB B
constexpr int SMEM_DATA = 1024;
constexpr int SMEM_TOTAL = SMEM_DATA + 3 * STAGE; // 197632

template <int MODE>
__global__ void __launch_bounds__(256, 1) tc_gemm(
    const uint8_t* __restrict__ Ab, const uint8_t* __restrict__ Bb,
    const uint8_t* __restrict__ A2b, const uint8_t* __restrict__ B2b,
    const uint8_t* __restrict__ A3b, const uint8_t* __restrict__ B3b,
    const float* __restrict__ bias, const float* __restrict__ bias2,
    const float* __restrict__ bias3,
    float* __restrict__ Cf, uint8_t* __restrict__ Cb, uint8_t* __restrict__ C2b,
    uint8_t* __restrict__ C3b,
    float* __restrict__ rs,
    int K, float alpha,
    size_t sAb, size_t sBb, size_t sC)
{
    extern __shared__ char smem[];
    const int tid = threadIdx.x;
    int m0, n0, cls = 0;
    size_t zb = 0;

    if (MODE == 1) {
        const int t = blockIdx.x;
        if (t < 512) {                       // Q/K projection tiles
            cls = t >> 8;
            const int r = t & 255;
            m0 = (r >> 2) << 8;              // token row tile (64)
            n0 = (r & 3) << 8;               // output-dim tile (4)
            if (cls == 1) { Ab = A2b; Bb = B2b; bias = bias2; Cb = C2b; }
        } else {                             // Vt tiles
            cls = 2;
            const int u = t - 512;
            zb = (size_t)(u >> 5);
            const int r = u & 31;
            m0 = (r >> 3) << 8;              // v tile (4)
            n0 = (r & 7) << 8;               // s tile (8)
            Ab = A3b; Bb = B3b + zb * 4194304u; bias = bias3; Cb = C3b;
        }
    } else {
        zb = blockIdx.z;
        m0 = blockIdx.y * 256;
        n0 = blockIdx.x * 256;
        Ab += zb * sAb;  Bb += zb * sBb;
    }
    const int NC = K >> 6;                    // 64-k chunks
    const size_t blkA0 = ((size_t)(m0 >> 8)) * NC;
    const size_t blkB0 = ((size_t)(n0 >> 8)) * NC;

#if defined(__CUDA_ARCH_FEAT_SM103_ALL)
    // ======================= tcgen05 path (sm_103a) ========================
    const uint32_t sb = smem_u32(smem);

    if (tid < 32) TCGEN05_ALLOC(sb + 0, 512);
    if (tid >= 32 && tid < 64) TCGEN05_RELINQUISH();
    if (tid == 0) {
#pragma unroll
        for (int s = 0; s < 3; ++s) {
            MBAR_INIT(sb + 8  + 8 * s, 1);   // full (tx-based)
            MBAR_INIT(sb + 32 + 8 * s, 1);   // mma done
        }
    }
    __syncthreads();
    uint32_t tmem;
    asm volatile("ld.shared.b32 %0, [%1];" : "=r"(tmem) : "r"(sb + 0));

    constexpr uint32_t IDESC =
        (1u << 4) | ((256 / 8) << 17) | ((128 / 16) << 24);

    if (tid < 32 && elect_one_pred()) {
        auto load_chunk = [&](int kc, int st) {
            const uint32_t full = sb + 8 + 8 * st;
            const uint32_t base = sb + SMEM_DATA + st * STAGE;
            MBAR_EXPECT(full, STAGE);
            bulk_ld(base,         Ab + ((blkA0 + kc) << 15), 32768, full);
            bulk_ld(base + OFF_B, Bb + ((blkB0 + kc) << 15), 32768, full);
        };

        load_chunk(0, 0);
        if (NC > 1) load_chunk(1, 1);
        if (NC > 2) load_chunk(2, 2);

        int fph[3] = {0, 0, 0}, mph[3] = {0, 0, 0};
        for (int c = 0; c < NC; ++c) {
            const int st = c % 3;
            MBAR_WAIT(sb + 8 + 8 * st, fph[st]);
            fph[st] ^= 1;

            const uint32_t base = sb + SMEM_DATA + st * STAGE;
            const uint64_t daA0 = MAKE_SMEM_DESC(base);
            const uint64_t daA1 = MAKE_SMEM_DESC(base + 16384);
            const uint64_t db   = MAKE_SMEM_DESC(base + OFF_B);
#pragma unroll
            for (int half = 0; half < 2; ++half) {
                const uint64_t da = half ? daA1 : daA0;
                const uint32_t dt = tmem + half * 256;
#pragma unroll
                for (int ks = 0; ks < 4; ++ks)
                    mma_f16_ss(dt, da + ks * 2, db + ks * 2, IDESC,
                               !(c == 0 && ks == 0));
            }
            TCGEN05_COMMIT(sb + 32 + 8 * st);

            if (c > 0) {
                const int sp = (c - 1) % 3;
                MBAR_WAIT(sb + 32 + 8 * sp, mph[sp]);
                mph[sp] ^= 1;
                if (c + 2 < NC) load_chunk(c + 2, sp);
            }
        }
        MBAR_WAIT(sb + 32 + 8 * ((NC - 1) % 3), mph[(NC - 1) % 3]);
    }
    __syncthreads();
    TCGEN05_FENCE_AFTER();

    // epilogue: warps 0-3 -> D0 (rows 0-127), warps 4-7 -> D1 (rows 128-255)
    {
        const int half = tid >> 7;
        const int w4   = (tid >> 5) & 3;
        const int lid  = tid & 31;
        const int m    = m0 + half * 128 + w4 * 32 + lid;
        const uint32_t dt = tmem + half * 256;
        float inv = 1.0f, lsum = 0.0f, bm = 0.0f;
        if (MODE == 4) inv = 1.0f / rs[zb * SEQ + m];
        if (MODE == 1 && cls == 2) bm = bias[m];
        for (int j0 = 0; j0 < 256; j0 += 64) {
            uint32_t r[64];
            TCGEN05_LD_32X32B_X32(r,      dt + j0);
            TCGEN05_LD_32X32B_X32(r + 32, dt + j0 + 32);
            TCGEN05_WAIT_LD();
            if (MODE == 4) {
                float4* dst = (float4*)(Cf + zb * sC + (size_t)m * DM + n0 + j0);
#pragma unroll
                for (int i = 0; i < 16; ++i) {
                    float4 v;
                    v.x = __uint_as_float(r[4 * i + 0]) * inv;
                    v.y = __uint_as_float(r[4 * i + 1]) * inv;
                    v.z = __uint_as_float(r[4 * i + 2]) * inv;
                    v.w = __uint_as_float(r[4 * i + 3]) * inv;
                    dst[i] = v;
                }
            } else {   // MODE 1 / 3: blocked fp16 store (64 vals = 128B row)
                uint32_t H[32];
#pragma unroll
                for (int i = 0; i < 64; i += 2) {
                    float v0, v1;
                    if (MODE == 3) {
                        v0 = __expf(__uint_as_float(r[i])     * alpha);
                        v1 = __expf(__uint_as_float(r[i + 1]) * alpha);
                        lsum += v0 + v1;
                    } else if (cls < 2) {
                        v0 = __uint_as_float(r[i])     + bias[n0 + j0 + i];
                        v1 = __uint_as_float(r[i + 1]) + bias[n0 + j0 + i + 1];
                    } else {
                        v0 = __uint_as_float(r[i])     + bm;
                        v1 = __uint_as_float(r[i + 1]) + bm;
                    }
                    H[i >> 1] = pkh2(__float2half(v0), __float2half(v1));
                }
                uint8_t* base;
                size_t blk;
                const int row = m & 255;
                if (MODE == 1 && cls < 2) {   // Q/K: 4MB/batch(by m), nkc = 16
                    base = Cb + (size_t)(m >> 11) * 4194304u;
                    blk  = ((((size_t)((m & 2047) >> 8)) * 16) + ((n0 + j0) >> 6)) << 15;
                } else if (MODE == 3) {       // P: 8MB/batch, nkc = 32
                    base = Cb + zb * 8388608u;
                    blk  = ((((size_t)(m >> 8)) * 32) + ((n0 + j0) >> 6)) << 15;
                } else {                      // Vt: 4MB/batch, nkc = 32
                    base = Cb + zb * 4194304u;
                    blk  = ((((size_t)(m >> 8)) * 32) + ((n0 + j0) >> 6)) << 15;
                }
#pragma unroll
                for (int q = 0; q < 8; ++q) {
                    uint4 hv;
                    hv.x = H[4*q]; hv.y = H[4*q+1]; hv.z = H[4*q+2]; hv.w = H[4*q+3];
                    *(uint4*)(base + blk +
                              SWZ128((uint32_t)row * 128 + q * 16)) = hv;
                }
            }
        }
        if (MODE == 3) atomicAdd(&rs[zb * SEQ + m], lsum);
    }
    __syncthreads();
    if (tid < 32) TCGEN05_DEALLOC(tmem, 512);

#elif defined(__CUDA_ARCH__)
    // ================= mma.sync fallback (base compute_103) =================
    // Correctness insurance only (sm_103a cubin is the one that runs).
    constexpr int STR = 20;
    constexpr int TILE_W = 128 * STR;
    constexpr int STAGE_W = 2 * TILE_W;
    const uint32_t sbase = smem_u32(smem);
    const int lane = tid & 31, wid = tid >> 5;
    const int wm = wid >> 1, wn = wid & 1;
    const int g = lane >> 2, tg = lane & 3;
    const int NC32 = K >> 5;

    auto load_chunk = [&](int c32, int st, int mbase, int nbase) {
        const int q = tid & 3, r0 = tid >> 2;
        const uint32_t dst0 = sbase + st * STAGE_W * 4;
        const int kc = c32 >> 1, h = c32 & 1;
#pragma unroll
        for (int i = 0; i < 2; ++i) {
            const int ra = mbase + r0 + 64 * i;
            const int rb = nbase + r0 + 64 * i;
            const uint32_t ro = (uint32_t)((r0 + 64 * i) * STR + q * 4) * 4;
            const size_t ba = (((size_t)(ra >> 8)) * NC + kc) << 15;
            const size_t bb = (((size_t)(rb >> 8)) * NC + kc) << 15;
            const uint32_t oa = (uint32_t)(ra & 255) * 128 + h * 64 + q * 16;
            const uint32_t ob = (uint32_t)(rb & 255) * 128 + h * 64 + q * 16;
            cp16(dst0 + ro,                Ab + ba + SWZ128(oa));
            cp16(dst0 + TILE_W * 4 + ro,   Bb + bb + SWZ128(ob));
        }
    };

    for (int mh = 0; mh < 2; ++mh) {
        const int mb0 = m0 + mh * 128;
        for (int np = 0; np < 2; ++np) {
            const int nb0 = n0 + np * 128;

            float acc[2][8][4];
#pragma unroll
            for (int a = 0; a < 2; ++a)
#pragma unroll
                for (int b = 0; b < 8; ++b)
#pragma unroll
                    for (int c = 0; c < 4; ++c) acc[a][b][c] = 0.0f;

            load_chunk(0, 0, mb0, nb0); CP_COMMIT();

            for (int c = 0; c < NC32; ++c) {
                const int st = c & 1;
                if (c + 1 < NC32) { load_chunk(c + 1, st ^ 1, mb0, nb0); CP_COMMIT(); CP_WAIT(1); }
                else              { CP_WAIT(0); }
                __syncthreads();

                const uint32_t* s0 = (const uint32_t*)smem + st * STAGE_W;
#pragma unroll
                for (int ks = 0; ks < 2; ++ks) {
                    uint32_t af[2][4];
#pragma unroll
                    for (int mt = 0; mt < 2; ++mt) {
                        const int rb = wm * 32 + mt * 16;
                        const uint32_t* pa = s0 + (rb + g) * STR + ks * 8 + tg;
                        af[mt][0] = pa[0];           af[mt][2] = pa[4];
                        af[mt][1] = pa[8 * STR];     af[mt][3] = pa[8 * STR + 4];
                    }
#pragma unroll
                    for (int nt = 0; nt < 8; ++nt) {
                        const int nb = wn * 64 + nt * 8;
                        const uint32_t* pb = s0 + TILE_W + (nb + g) * STR + ks * 8 + tg;
                        const uint32_t b0 = pb[0], b1 = pb[4];
#pragma unroll
                        for (int mt = 0; mt < 2; ++mt)
                            mma16816h(acc[mt][nt], af[mt], b0, b1);
                    }
                }
                __syncthreads();
            }

#pragma unroll
            for (int mt = 0; mt < 2; ++mt) {
#pragma unroll
                for (int nt = 0; nt < 8; ++nt) {
                    const int m1 = mb0 + wm * 32 + mt * 16 + g;
                    const int m2 = m1 + 8;
                    const int n  = nb0 + wn * 64 + nt * 8 + tg * 2;
                    const float* a = acc[mt][nt];
                    if (MODE == 4) {
                        const float i1 = 1.0f / rs[zb * SEQ + m1];
                        const float i2 = 1.0f / rs[zb * SEQ + m2];
                        float2 v0; v0.x = a[0] * i1; v0.y = a[1] * i1;
                        float2 v1; v1.x = a[2] * i2; v1.y = a[3] * i2;
                        *(float2*)(Cf + zb * sC + (size_t)m1 * DM + n) = v0;
                        *(float2*)(Cf + zb * sC + (size_t)m2 * DM + n) = v1;
                    } else if (MODE == 1 && cls < 2) {
#pragma unroll
                        for (int e = 0; e < 4; ++e) {
                            const int m = (e < 2) ? m1 : m2;
                            const int nn = n + (e & 1);
                            store_blk1(Cb + (size_t)(m >> 11) * 4194304u,
                                       m & 2047, nn, 16, a[e] + bias[nn]);
                        }
                    } else if (MODE == 3) {
                        float e0 = __expf(a[0] * alpha), e1 = __expf(a[1] * alpha);
                        float e2 = __expf(a[2] * alpha), e3 = __expf(a[3] * alpha);
                        atomicAdd(&rs[zb * SEQ + m1], e0 + e1);
                        atomicAdd(&rs[zb * SEQ + m2], e2 + e3);
                        uint8_t* base = Cb + zb * 8388608u;
                        store_blk1(base, m1, n,     32, e0);
                        store_blk1(base, m1, n + 1, 32, e1);
                        store_blk1(base, m2, n,     32, e2);
                        store_blk1(base, m2, n + 1, 32, e3);
                    } else {  // MODE 1, cls == 2 (Vt)
                        uint8_t* base = Cb + zb * 4194304u;
#pragma unroll
                        for (int e = 0; e < 4; ++e) {
                            const int m = (e < 2) ? m1 : m2;
                            const int nn = n + (e & 1);
                            store_blk1(base, m, nn, 32, a[e] + bias[m]);
                        }
                    }
                }
            }
            __syncthreads();
        }
    }
#endif
}

// ---------------------------------------------------------------------------
// f32 -> blocked fp16 (K fixed = 1024; nkc = 16). z selects among 3 tensors.
// 4 units per iteration, loads front-loaded (MLP=8). Optionally zeros rs.
// ---------------------------------------------------------------------------
__global__ void __launch_bounds__(256) split3_k(
    const float* __restrict__ x0, const float* __restrict__ x1,
    const float* __restrict__ x2,
    uint8_t* __restrict__ d0, uint8_t* __restrict__ d1,
    uint8_t* __restrict__ d2, int nunits,
    float* __restrict__ rs, int nrs)
{
    const int z = blockIdx.z;
    if (rs && z == 0) {
        const int i = blockIdx.x * 256 + threadIdx.x;
        if (i < nrs) rs[i] = 0.0f;
    }
    const float* x = (z == 0) ? x0 : (z == 1) ? x1 : x2;
    uint8_t*   dst = (z == 0) ? d0 : (z == 1) ? d1 : d2;
    const int stride = (int)gridDim.x * 256;
    int u0 = blockIdx.x * 256 + threadIdx.x;

    for (; u0 + 3 * stride < nunits; u0 += 4 * stride) {
        float4 f[8];
#pragma unroll
        for (int k = 0; k < 4; ++k) {
            const int u = u0 + k * stride;
            const int r = u >> 7, j = u & 127;
            const float* p = x + ((size_t)r << 10) + (j << 3);
            f[2 * k]     = *(const float4*)p;
            f[2 * k + 1] = *(const float4*)(p + 4);
        }
#pragma unroll
        for (int k = 0; k < 4; ++k) {
            const int u = u0 + k * stride;
            const int r = u >> 7, j = u & 127;
            uint4 hv;
            hv.x = pkh2(__float2half(f[2*k].x),   __float2half(f[2*k].y));
            hv.y = pkh2(__float2half(f[2*k].z),   __float2half(f[2*k].w));
            hv.z = pkh2(__float2half(f[2*k+1].x), __float2half(f[2*k+1].y));
            hv.w = pkh2(__float2half(f[2*k+1].z), __float2half(f[2*k+1].w));
            const size_t blk = ((((size_t)(r >> 8)) << 4) + (j >> 3)) << 15;
            const uint32_t ro = (uint32_t)(r & 255) * 128 + (j & 7) * 16;
            *(uint4*)(dst + blk + SWZ128(ro)) = hv;
        }
    }
    for (; u0 < nunits; u0 += stride) {
        const int r = u0 >> 7, j = u0 & 127;
        const float4 f0 = *(const float4*)(x + ((size_t)r << 10) + (j << 3));
        const float4 f1 = *(const float4*)(x + ((size_t)r << 10) + (j << 3) + 4);
        uint4 hv;
        hv.x = pkh2(__float2half(f0.x), __float2half(f0.y));
        hv.y = pkh2(__float2half(f0.z), __float2half(f0.w));
        hv.z = pkh2(__float2half(f1.x), __float2half(f1.y));
        hv.w = pkh2(__float2half(f1.z), __float2half(f1.w));
        const size_t blk = ((((size_t)(r >> 8)) << 4) + (j >> 3)) << 15;
        const uint32_t ro = (uint32_t)(r & 255) * 128 + (j & 7) * 16;
        *(uint4*)(dst + blk + SWZ128(ro)) = hv;
    }
}

// ---------------------------------------------------------------------------
extern "C" void kernel_launch(void* const* d_in, const int* in_sizes, int n_in,
                              void* d_out, int out_size)
{
    (void)in_sizes; (void)n_in; (void)out_size;
    const float* q  = (const float*)d_in[0];
    const float* kx = (const float*)d_in[1];
    const float* vx = (const float*)d_in[2];
    const float* Wq = (const float*)d_in[3];
    const float* bq = (const float*)d_in[4];
    const float* Wk = (const float*)d_in[5];
    const float* bk = (const float*)d_in[6];
    const float* Wv = (const float*)d_in[7];
    const float* bv = (const float*)d_in[8];
    float* out = (float*)d_out;

    uint8_t *Xq, *Xk, *Xv, *Wqb, *Wkb, *Wvb, *Qb, *Kb, *Vt, *Pb;
    float* rs;
    cudaGetSymbolAddress((void**)&Xq,  g_Xq);  cudaGetSymbolAddress((void**)&Xk,  g_Xk);
    cudaGetSymbolAddress((void**)&Xv,  g_Xv);
    cudaGetSymbolAddress((void**)&Wqb, g_Wq);  cudaGetSymbolAddress((void**)&Wkb, g_Wk);
    cudaGetSymbolAddress((void**)&Wvb, g_Wv);
    cudaGetSymbolAddress((void**)&Qb,  g_Qb);  cudaGetSymbolAddress((void**)&Kb,  g_Kb);
    cudaGetSymbolAddress((void**)&Vt,  g_Vt);  cudaGetSymbolAddress((void**)&Pb,  g_Pb);
    cudaGetSymbolAddress((void**)&rs,  g_rs);

    cudaFuncSetAttribute(tc_gemm<1>, cudaFuncAttributeMaxDynamicSharedMemorySize, SMEM_TOTAL);
    cudaFuncSetAttribute(tc_gemm<3>, cudaFuncAttributeMaxDynamicSharedMemorySize, SMEM_TOTAL);
    cudaFuncSetAttribute(tc_gemm<4>, cudaFuncAttributeMaxDynamicSharedMemorySize, SMEM_TOTAL);

    // 1. splits (inputs; weights launch also zeros rs)
    split3_k<<<dim3(512, 1, 3), 256>>>(q, kx, vx, Xq, Xk, Xv,
                                       NTOK * DIN / 8, nullptr, 0);
    split3_k<<<dim3(128, 1, 3), 256>>>(Wq, Wk, Wv, Wqb, Wkb, Wvb,
                                       DM * DIN / 8, rs, BN * SEQ);

    // 2. MERGED Q-proj + K-proj + Vt in one 768-tile launch
    tc_gemm<1><<<768, 256, SMEM_TOTAL>>>(
        Xq, Wqb, Xk, Wkb, Wvb, Xv,
        bq, bk, bv,
        nullptr, Qb, Kb, Vt, nullptr,
        DIN, 1.0f, 0, 0, 0);

    // 3. scores + exp + row sums -> fp16 P
    tc_gemm<3><<<dim3(SEQ / 256, SEQ / 256, BN), 256, SMEM_TOTAL>>>(
        Qb, Kb, nullptr, nullptr, nullptr, nullptr,
        nullptr, nullptr, nullptr,
        nullptr, Pb, nullptr, nullptr, rs,
        DM, 0.03125f, 4194304u, 4194304u, 0);

    // 4. O = (P * Vt^T) / rowsum
    tc_gemm<4><<<dim3(DM / 256, SEQ / 256, BN), 256, SMEM_TOTAL>>>(
        Pb, Vt, nullptr, nullptr, nullptr, nullptr,
        nullptr, nullptr, nullptr,
        out, nullptr, nullptr, nullptr, rs,
        SEQ, 1.0f, 8388608u, 4194304u, (size_t)SEQ * DM);
}

// round 16
// speedup vs baseline: 1.0824x; 1.0208x over previous
#include <cuda_runtime.h>
#include <cuda_bf16.h>
#include <cuda_fp16.h>
#include <cstdint>

// ---------------------------------------------------------------------------
// Problem constants
// ---------------------------------------------------------------------------
#define BN   8
#define SEQ  2048
#define DIN  1024
#define DM   1024
#define NTOK (BN*SEQ)          // 16384

// ---------------------------------------------------------------------------
// Blocked fp16 operand layout (round-9/12 validated):
//   operand[row, k] stored as 32KB blocks indexed [row/256][k/64].
//   Block: 256 rows x 128B; row = 64 fp16 k-values, SW128-swizzled.
//   GEMM chunk (K=64) load = TWO contiguous 32KB cp.async.bulk copies.
// Round-16: PDL (programmatic dependent launch) on every boundary; dependents
//   run their prologue during the producer's tail and gate data reads with
//   griddepcontrol.wait. Splits overlap fully (independent).
// ---------------------------------------------------------------------------
#define SWZ128(off) ((off) ^ (((off) >> 3) & 0x70))

__device__ uint8_t g_Xq[(size_t)NTOK*DIN*2];
__device__ uint8_t g_Xk[(size_t)NTOK*DIN*2];
__device__ uint8_t g_Xv[(size_t)NTOK*DIN*2];
__device__ uint8_t g_Wq[(size_t)DM*DIN*2];
__device__ uint8_t g_Wk[(size_t)DM*DIN*2];
__device__ uint8_t g_Wv[(size_t)DM*DIN*2];
__device__ uint8_t g_Qb[(size_t)NTOK*DM*2];          // 4MB/batch, nkc=16
__device__ uint8_t g_Kb[(size_t)NTOK*DM*2];
__device__ uint8_t g_Vt[(size_t)BN*DM*SEQ*2];        // rows=v, k=s, nkc=32, 4MB/batch
__device__ uint8_t g_Pb[(size_t)BN*SEQ*SEQ*2];       // rows=q, k=s, nkc=32, 8MB/batch
__device__ float   g_rs[(size_t)BN*SEQ];

// ---------------------------------------------------------------------------
// PDL primitives (sm_90+ PTX, fine under compute_103)
// ---------------------------------------------------------------------------
#define PDL_TRIGGER() asm volatile("griddepcontrol.launch_dependents;" ::: "memory")
#define PDL_WAIT()    asm volatile("griddepcontrol.wait;" ::: "memory")

// ---------------------------------------------------------------------------
// Helpers available on base compute_103
// ---------------------------------------------------------------------------
__device__ __forceinline__ uint32_t smem_u32(const void* p) {
    uint32_t a;
    asm("{ .reg .u64 t; cvta.to.shared.u64 t, %1; cvt.u32.u64 %0, t; }"
        : "=r"(a) : "l"(p));
    return a;
}
__device__ __forceinline__ void cp16(uint32_t dst, const void* src) {
    asm volatile("cp.async.cg.shared.global [%0], [%1], 16;" :: "r"(dst), "l"(src));
}
#define CP_COMMIT()  asm volatile("cp.async.commit_group;" ::: "memory")
#define CP_WAIT(N)   asm volatile("cp.async.wait_group %0;" :: "n"(N) : "memory")

__device__ __forceinline__ void mma16816h(float* c, const uint32_t* a,
                                          uint32_t b0, uint32_t b1) {
    asm volatile(
        "mma.sync.aligned.m16n8k16.row.col.f32.f16.f16.f32 "
        "{%0,%1,%2,%3}, {%4,%5,%6,%7}, {%8,%9}, {%0,%1,%2,%3};"
        : "+f"(c[0]), "+f"(c[1]), "+f"(c[2]), "+f"(c[3])
        : "r"(a[0]), "r"(a[1]), "r"(a[2]), "r"(a[3]), "r"(b0), "r"(b1));
}

__device__ __forceinline__ uint32_t pkh2(__half a, __half b) {
    __half2 t; t.x = a; t.y = b;
    return *(uint32_t*)&t;
}
// scalar fp16 store into blocked layout (fallback path)
__device__ __forceinline__ void store_blk1(uint8_t* base, int row, int k,
                                           int nkc, float v) {
    const size_t blk = (((size_t)(row >> 8)) * nkc + (k >> 6)) << 15;
    const uint32_t off = (uint32_t)(row & 255) * 128 + (k & 63) * 2;
    *(__half*)(base + blk + SWZ128(off)) = __float2half(v);
}

// bulk copy (UBLKCP): contiguous gmem -> smem, completion via mbarrier tx-bytes
__device__ __forceinline__ void bulk_ld(uint32_t dst, const void* src,
                                        uint32_t bytes, uint32_t mbar) {
    asm volatile(
        "cp.async.bulk.shared::cluster.global.mbarrier::complete_tx::bytes "
        "[%0], [%1], %2, [%3];"
        :: "r"(dst), "l"(src), "r"(bytes), "r"(mbar) : "memory");
}
#define MBAR_INIT(addr, cnt) \
    asm volatile("mbarrier.init.shared.b64 [%0], %1;" :: "r"((uint32_t)(addr)), "r"((uint32_t)(cnt)) : "memory")
#define MBAR_EXPECT(addr, tx) \
    asm volatile("mbarrier.arrive.expect_tx.shared.b64 _, [%0], %1;" :: "r"((uint32_t)(addr)), "r"((uint32_t)(tx)) : "memory")
#define MBAR_WAIT(mbar, par) do { \
    uint32_t _m = (uint32_t)(mbar), _p = (uint32_t)(par), _d; \
    asm volatile("{\n\t.reg .pred p;\n\t" \
        "mbarrier.try_wait.parity.acquire.cta.shared::cta.b64 p, [%1], %2;\n\t" \
        "selp.b32 %0, 1, 0, p;\n\t}" : "=r"(_d) : "r"(_m), "r"(_p) : "memory"); \
    if (!_d) { \
        asm volatile("{\n\t.reg .pred P1;\n\t" \
            "WL_%=:\n\t" \
            "mbarrier.try_wait.parity.acquire.cta.shared::cta.b64 P1, [%0], %1, 0x989680;\n\t" \
            "@P1 bra.uni WD_%=;\n\tbra.uni WL_%=;\n\tWD_%=:\n\t}" \
            :: "r"(_m), "r"(_p) : "memory"); \
    } \
} while (0)

// ---------------------------------------------------------------------------
// tcgen05 helpers — ONLY compiled when the build has a compute_103a pass.
// ---------------------------------------------------------------------------
#if defined(__CUDA_ARCH_FEAT_SM103_ALL)
__device__ __forceinline__ uint32_t elect_one_pred() {
    uint32_t pred;
    asm volatile(
        "{\n\t.reg .pred p;\n\t"
        "elect.sync _|p, 0xFFFFFFFF;\n\t"
        "selp.b32 %0, 1, 0, p;\n\t}"
        : "=r"(pred));
    return pred;
}
#define TCGEN05_ALLOC(a, n) \
    asm volatile("tcgen05.alloc.cta_group::1.sync.aligned.shared::cta.b32 [%0], %1;" \
        :: "r"((uint32_t)(a)), "r"((uint32_t)(n)) : "memory")
#define TCGEN05_RELINQUISH() \
    asm volatile("tcgen05.relinquish_alloc_permit.cta_group::1.sync.aligned;")
#define TCGEN05_DEALLOC(t, n) \
    asm volatile("tcgen05.dealloc.cta_group::1.sync.aligned.b32 %0, %1;" :: "r"(t), "r"((uint32_t)(n)))
#define TCGEN05_COMMIT(m) \
    asm volatile("tcgen05.commit.cta_group::1.mbarrier::arrive::one.shared::cluster.b64 [%0];" \
        :: "r"((uint32_t)(m)) : "memory")
#define TCGEN05_WAIT_LD()    asm volatile("tcgen05.wait::ld.sync.aligned;" ::: "memory")
#define TCGEN05_FENCE_AFTER() asm volatile("tcgen05.fence::after_thread_sync;" ::: "memory")
#define TCGEN05_LD_32X32B_X32(r, ta) \
    asm volatile( \
        "tcgen05.ld.sync.aligned.32x32b.x32.b32 " \
        "{%0, %1, %2, %3, %4, %5, %6, %7, " \
        " %8, %9, %10, %11, %12, %13, %14, %15, " \
        " %16, %17, %18, %19, %20, %21, %22, %23, " \
        " %24, %25, %26, %27, %28, %29, %30, %31}, [%32];" \
        : "=r"((r)[0]),  "=r"((r)[1]),  "=r"((r)[2]),  "=r"((r)[3]), \
          "=r"((r)[4]),  "=r"((r)[5]),  "=r"((r)[6]),  "=r"((r)[7]), \
          "=r"((r)[8]),  "=r"((r)[9]),  "=r"((r)[10]), "=r"((r)[11]), \
          "=r"((r)[12]), "=r"((r)[13]), "=r"((r)[14]), "=r"((r)[15]), \
          "=r"((r)[16]), "=r"((r)[17]), "=r"((r)[18]), "=r"((r)[19]), \
          "=r"((r)[20]), "=r"((r)[21]), "=r"((r)[22]), "=r"((r)[23]), \
          "=r"((r)[24]), "=r"((r)[25]), "=r"((r)[26]), "=r"((r)[27]), \
          "=r"((r)[28]), "=r"((r)[29]), "=r"((r)[30]), "=r"((r)[31]) \
        : "r"(ta))
static constexpr uint64_t SMEM_DESC_BASE_SW128 =
    (uint64_t(2)  << 61) | (uint64_t(1) << 46) | (uint64_t(64) << 32) | (uint64_t(1) << 16);
#define MAKE_SMEM_DESC(ba) (SMEM_DESC_BASE_SW128 | ((uint64_t)((ba) >> 4) & 0x3FFF))
__device__ __forceinline__ void mma_f16_ss(uint32_t d, uint64_t ad, uint64_t bd,
                                           uint32_t idesc, bool acc) {
    uint32_t en = acc ? 1u : 0u;
    asm volatile(
        "{\n\t.reg .pred p;\n\t"
        "setp.ne.u32 p, %5, 0;\n\t"
        "tcgen05.mma.cta_group::1.kind::f16 [%0], %1, %2, %3, {%4, %4, %4, %4}, p;\n\t"
        "}"
        :: "r"(d), "l"(ad), "l"(bd), "r"(idesc), "r"(0u), "r"(en)
        : "memory");
}
#endif  // __CUDA_ARCH_FEAT_SM103_ALL

// ---------------------------------------------------------------------------
// GEMM: C[M,N] = A[M,K] * B[N,K]^T, single-pass fp16 operands (blocked).
// tcgen05: CTA 256x256, TK=64, two M=128 TMEM accumulators, 3-stage pipeline,
// 2x32KB bulk loads/chunk, single-elected-thread mainloop, deferred MMA wait.
// PDL: trigger at entry; wait after prologue, before first dependent read.
// MODE 1: MERGED projections, 1-D grid of 768 tiles:
//   t<512  : Q/K proj (cls=t>>8): A=X?, B=W?, bias[n], out blocked nkc=16
//   t>=512 : Vt tile: A=Wv, B=Xv(batch), bias[m], out Vt nkc=32 (4MB/batch)
// MODE 3: e=expf(acc*alpha) f16 out + row-sum atomics [scores->P], nkc=32
// MODE 4: f32 out = acc / rowsum[m]  [PV]
// ---------------------------------------------------------------------------
constexpr int OFF_B  = 32768;
constexpr int STAGE  = 65536;                     // 32KB A + 32KB B
constexpr int SMEM_DATA = 1024;
constexpr int SMEM_TOTAL = SMEM_DATA + 3 * STAGE; // 197632

template <int MODE>
__global__ void __launch_bounds__(256, 1) tc_gemm(
    const uint8_t* __restrict__ Ab, const uint8_t* __restrict__ Bb,
    const uint8_t* __restrict__ A2b, const uint8_t* __restrict__ B2b,
    const uint8_t* __restrict__ A3b, const uint8_t* __restrict__ B3b,
    const float* __restrict__ bias, const float* __restrict__ bias2,
    const float* __restrict__ bias3,
    float* __restrict__ Cf, uint8_t* __restrict__ Cb, uint8_t* __restrict__ C2b,
    uint8_t* __restrict__ C3b,
    float* __restrict__ rs,
    int K, float alpha,
    size_t sAb, size_t sBb, size_t sC)
{
    extern __shared__ char smem[];
    const int tid = threadIdx.x;
    PDL_TRIGGER();                 // let the next kernel begin its prologue
    int m0, n0, cls = 0;
    size_t zb = 0;

    if (MODE == 1) {
        const int t = blockIdx.x;
        if (t < 512) {                       // Q/K projection tiles
            cls = t >> 8;
            const int r = t & 255;
            m0 = (r >> 2) << 8;              // token row tile (64)
            n0 = (r & 3) << 8;               // output-dim tile (4)
            if (cls == 1) { Ab = A2b; Bb = B2b; bias = bias2; Cb = C2b; }
        } else {                             // Vt tiles
            cls = 2;
            const int u = t - 512;
            zb = (size_t)(u >> 5);
            const int r = u & 31;
            m0 = (r >> 3) << 8;              // v tile (4)
            n0 = (r & 7) << 8;               // s tile (8)
            Ab = A3b; Bb = B3b + zb * 4194304u; bias = bias3; Cb = C3b;
        }
    } else {
        zb = blockIdx.z;
        m0 = blockIdx.y * 256;
        n0 = blockIdx.x * 256;
        Ab += zb * sAb;  Bb += zb * sBb;
    }
    const int NC = K >> 6;                    // 64-k chunks
    const size_t blkA0 = ((size_t)(m0 >> 8)) * NC;
    const size_t blkB0 = ((size_t)(n0 >> 8)) * NC;

#if defined(__CUDA_ARCH_FEAT_SM103_ALL)
    // ======================= tcgen05 path (sm_103a) ========================
    const uint32_t sb = smem_u32(smem);

    if (tid < 32) TCGEN05_ALLOC(sb + 0, 512);
    if (tid >= 32 && tid < 64) TCGEN05_RELINQUISH();
    if (tid == 0) {
#pragma unroll
        for (int s = 0; s < 3; ++s) {
            MBAR_INIT(sb + 8  + 8 * s, 1);   // full (tx-based)
            MBAR_INIT(sb + 32 + 8 * s, 1);   // mma done
        }
    }
    __syncthreads();
    uint32_t tmem;
    asm volatile("ld.shared.b32 %0, [%1];" : "=r"(tmem) : "r"(sb + 0));

    PDL_WAIT();                    // producer grid's memory now visible

    constexpr uint32_t IDESC =
        (1u << 4) | ((256 / 8) << 17) | ((128 / 16) << 24);

    if (tid < 32 && elect_one_pred()) {
        auto load_chunk = [&](int kc, int st) {
            const uint32_t full = sb + 8 + 8 * st;
            const uint32_t base = sb + SMEM_DATA + st * STAGE;
            MBAR_EXPECT(full, STAGE);
            bulk_ld(base,         Ab + ((blkA0 + kc) << 15), 32768, full);
            bulk_ld(base + OFF_B, Bb + ((blkB0 + kc) << 15), 32768, full);
        };

        load_chunk(0, 0);
        if (NC > 1) load_chunk(1, 1);
        if (NC > 2) load_chunk(2, 2);

        int fph[3] = {0, 0, 0}, mph[3] = {0, 0, 0};
        for (int c = 0; c < NC; ++c) {
            const int st = c % 3;
            MBAR_WAIT(sb + 8 + 8 * st, fph[st]);
            fph[st] ^= 1;

            const uint32_t base = sb + SMEM_DATA + st * STAGE;
            const uint64_t daA0 = MAKE_SMEM_DESC(base);
            const uint64_t daA1 = MAKE_SMEM_DESC(base + 16384);
            const uint64_t db   = MAKE_SMEM_DESC(base + OFF_B);
#pragma unroll
            for (int half = 0; half < 2; ++half) {
                const uint64_t da = half ? daA1 : daA0;
                const uint32_t dt = tmem + half * 256;
#pragma unroll
                for (int ks = 0; ks < 4; ++ks)
                    mma_f16_ss(dt, da + ks * 2, db + ks * 2, IDESC,
                               !(c == 0 && ks == 0));
            }
            TCGEN05_COMMIT(sb + 32 + 8 * st);

            if (c > 0) {
                const int sp = (c - 1) % 3;
                MBAR_WAIT(sb + 32 + 8 * sp, mph[sp]);
                mph[sp] ^= 1;
                if (c + 2 < NC) load_chunk(c + 2, sp);
            }
        }
        MBAR_WAIT(sb + 32 + 8 * ((NC - 1) % 3), mph[(NC - 1) % 3]);
    }
    __syncthreads();
    TCGEN05_FENCE_AFTER();

    // epilogue: warps 0-3 -> D0 (rows 0-127), warps 4-7 -> D1 (rows 128-255)
    {
        const int half = tid >> 7;
        const int w4   = (tid >> 5) & 3;
        const int lid  = tid & 31;
        const int m    = m0 + half * 128 + w4 * 32 + lid;
        const uint32_t dt = tmem + half * 256;
        float inv = 1.0f, lsum = 0.0f, bm = 0.0f;
        if (MODE == 4) inv = 1.0f / rs[zb * SEQ + m];
        if (MODE == 1 && cls == 2) bm = bias[m];
        for (int j0 = 0; j0 < 256; j0 += 64) {
            uint32_t r[64];
            TCGEN05_LD_32X32B_X32(r,      dt + j0);
            TCGEN05_LD_32X32B_X32(r + 32, dt + j0 + 32);
            TCGEN05_WAIT_LD();
            if (MODE == 4) {
                float4* dst = (float4*)(Cf + zb * sC + (size_t)m * DM + n0 + j0);
#pragma unroll
                for (int i = 0; i < 16; ++i) {
                    float4 v;
                    v.x = __uint_as_float(r[4 * i + 0]) * inv;
                    v.y = __uint_as_float(r[4 * i + 1]) * inv;
                    v.z = __uint_as_float(r[4 * i + 2]) * inv;
                    v.w = __uint_as_float(r[4 * i + 3]) * inv;
                    dst[i] = v;
                }
            } else {   // MODE 1 / 3: blocked fp16 store (64 vals = 128B row)
                uint32_t H[32];
#pragma unroll
                for (int i = 0; i < 64; i += 2) {
                    float v0, v1;
                    if (MODE == 3) {
                        v0 = __expf(__uint_as_float(r[i])     * alpha);
                        v1 = __expf(__uint_as_float(r[i + 1]) * alpha);
                        lsum += v0 + v1;
                    } else if (cls < 2) {
                        v0 = __uint_as_float(r[i])     + bias[n0 + j0 + i];
                        v1 = __uint_as_float(r[i + 1]) + bias[n0 + j0 + i + 1];
                    } else {
                        v0 = __uint_as_float(r[i])     + bm;
                        v1 = __uint_as_float(r[i + 1]) + bm;
                    }
                    H[i >> 1] = pkh2(__float2half(v0), __float2half(v1));
                }
                uint8_t* base;
                size_t blk;
                const int row = m & 255;
                if (MODE == 1 && cls < 2) {   // Q/K: 4MB/batch(by m), nkc = 16
                    base = Cb + (size_t)(m >> 11) * 4194304u;
                    blk  = ((((size_t)((m & 2047) >> 8)) * 16) + ((n0 + j0) >> 6)) << 15;
                } else if (MODE == 3) {       // P: 8MB/batch, nkc = 32
                    base = Cb + zb * 8388608u;
                    blk  = ((((size_t)(m >> 8)) * 32) + ((n0 + j0) >> 6)) << 15;
                } else {                      // Vt: 4MB/batch, nkc = 32
                    base = Cb + zb * 4194304u;
                    blk  = ((((size_t)(m >> 8)) * 32) + ((n0 + j0) >> 6)) << 15;
                }
#pragma unroll
                for (int q = 0; q < 8; ++q) {
                    uint4 hv;
                    hv.x = H[4*q]; hv.y = H[4*q+1]; hv.z = H[4*q+2]; hv.w = H[4*q+3];
                    *(uint4*)(base + blk +
                              SWZ128((uint32_t)row * 128 + q * 16)) = hv;
                }
            }
        }
        if (MODE == 3) atomicAdd(&rs[zb * SEQ + m], lsum);
    }
    __syncthreads();
    if (tid < 32) TCGEN05_DEALLOC(tmem, 512);

#elif defined(__CUDA_ARCH__)
    // ================= mma.sync fallback (base compute_103) =================
    // Correctness insurance only (sm_103a cubin is the one that runs).
    constexpr int STR = 20;
    constexpr int TILE_W = 128 * STR;
    constexpr int STAGE_W = 2 * TILE_W;
    const uint32_t sbase = smem_u32(smem);
    const int lane = tid & 31, wid = tid >> 5;
    const int wm = wid >> 1, wn = wid & 1;
    const int g = lane >> 2, tg = lane & 3;
    const int NC32 = K >> 5;

    PDL_WAIT();

    auto load_chunk = [&](int c32, int st, int mbase, int nbase) {
        const int q = tid & 3, r0 = tid >> 2;
        const uint32_t dst0 = sbase + st * STAGE_W * 4;
        const int kc = c32 >> 1, h = c32 & 1;
#pragma unroll
        for (int i = 0; i < 2; ++i) {
            const int ra = mbase + r0 + 64 * i;
            const int rb = nbase + r0 + 64 * i;
            const uint32_t ro = (uint32_t)((r0 + 64 * i) * STR + q * 4) * 4;
            const size_t ba = (((size_t)(ra >> 8)) * NC + kc) << 15;
            const size_t bb = (((size_t)(rb >> 8)) * NC + kc) << 15;
            const uint32_t oa = (uint32_t)(ra & 255) * 128 + h * 64 + q * 16;
            const uint32_t ob = (uint32_t)(rb & 255) * 128 + h * 64 + q * 16;
            cp16(dst0 + ro,                Ab + ba + SWZ128(oa));
            cp16(dst0 + TILE_W * 4 + ro,   Bb + bb + SWZ128(ob));
        }
    };

    for (int mh = 0; mh < 2; ++mh) {
        const int mb0 = m0 + mh * 128;
        for (int np = 0; np < 2; ++np) {
            const int nb0 = n0 + np * 128;

            float acc[2][8][4];
#pragma unroll
            for (int a = 0; a < 2; ++a)
#pragma unroll
                for (int b = 0; b < 8; ++b)
#pragma unroll
                    for (int c = 0; c < 4; ++c) acc[a][b][c] = 0.0f;

            load_chunk(0, 0, mb0, nb0); CP_COMMIT();

            for (int c = 0; c < NC32; ++c) {
                const int st = c & 1;
                if (c + 1 < NC32) { load_chunk(c + 1, st ^ 1, mb0, nb0); CP_COMMIT(); CP_WAIT(1); }
                else              { CP_WAIT(0); }
                __syncthreads();

                const uint32_t* s0 = (const uint32_t*)smem + st * STAGE_W;
#pragma unroll
                for (int ks = 0; ks < 2; ++ks) {
                    uint32_t af[2][4];
#pragma unroll
                    for (int mt = 0; mt < 2; ++mt) {
                        const int rb = wm * 32 + mt * 16;
                        const uint32_t* pa = s0 + (rb + g) * STR + ks * 8 + tg;
                        af[mt][0] = pa[0];           af[mt][2] = pa[4];
                        af[mt][1] = pa[8 * STR];     af[mt][3] = pa[8 * STR + 4];
                    }
#pragma unroll
                    for (int nt = 0; nt < 8; ++nt) {
                        const int nb = wn * 64 + nt * 8;
                        const uint32_t* pb = s0 + TILE_W + (nb + g) * STR + ks * 8 + tg;
                        const uint32_t b0 = pb[0], b1 = pb[4];
#pragma unroll
                        for (int mt = 0; mt < 2; ++mt)
                            mma16816h(acc[mt][nt], af[mt], b0, b1);
                    }
                }
                __syncthreads();
            }

#pragma unroll
            for (int mt = 0; mt < 2; ++mt) {
#pragma unroll
                for (int nt = 0; nt < 8; ++nt) {
                    const int m1 = mb0 + wm * 32 + mt * 16 + g;
                    const int m2 = m1 + 8;
                    const int n  = nb0 + wn * 64 + nt * 8 + tg * 2;
                    const float* a = acc[mt][nt];
                    if (MODE == 4) {
                        const float i1 = 1.0f / rs[zb * SEQ + m1];
                        const float i2 = 1.0f / rs[zb * SEQ + m2];
                        float2 v0; v0.x = a[0] * i1; v0.y = a[1] * i1;
                        float2 v1; v1.x = a[2] * i2; v1.y = a[3] * i2;
                        *(float2*)(Cf + zb * sC + (size_t)m1 * DM + n) = v0;
                        *(float2*)(Cf + zb * sC + (size_t)m2 * DM + n) = v1;
                    } else if (MODE == 1 && cls < 2) {
#pragma unroll
                        for (int e = 0; e < 4; ++e) {
                            const int m = (e < 2) ? m1 : m2;
                            const int nn = n + (e & 1);
                            store_blk1(Cb + (size_t)(m >> 11) * 4194304u,
                                       m & 2047, nn, 16, a[e] + bias[nn]);
                        }
                    } else if (MODE == 3) {
                        float e0 = __expf(a[0] * alpha), e1 = __expf(a[1] * alpha);
                        float e2 = __expf(a[2] * alpha), e3 = __expf(a[3] * alpha);
                        atomicAdd(&rs[zb * SEQ + m1], e0 + e1);
                        atomicAdd(&rs[zb * SEQ + m2], e2 + e3);
                        uint8_t* base = Cb + zb * 8388608u;
                        store_blk1(base, m1, n,     32, e0);
                        store_blk1(base, m1, n + 1, 32, e1);
                        store_blk1(base, m2, n,     32, e2);
                        store_blk1(base, m2, n + 1, 32, e3);
                    } else {  // MODE 1, cls == 2 (Vt)
                        uint8_t* base = Cb + zb * 4194304u;
#pragma unroll
                        for (int e = 0; e < 4; ++e) {
                            const int m = (e < 2) ? m1 : m2;
                            const int nn = n + (e & 1);
                            store_blk1(base, m, nn, 32, a[e] + bias[m]);
                        }
                    }
                }
            }
            __syncthreads();
        }
    }
#endif
}

// ---------------------------------------------------------------------------
// f32 -> blocked fp16 (K fixed = 1024; nkc = 16). z selects among 3 tensors.
// 4 units per iteration, loads front-loaded (MLP=8). Optionally zeros rs.
// Reads only harness inputs -> no PDL wait; triggers for downstream overlap.
// ---------------------------------------------------------------------------
__global__ void __launch_bounds__(256) split3_k(
    const float* __restrict__ x0, const float* __restrict__ x1,
    const float* __restrict__ x2,
    uint8_t* __restrict__ d0, uint8_t* __restrict__ d1,
    uint8_t* __restrict__ d2, int nunits,
    float* __restrict__ rs, int nrs)
{
    PDL_TRIGGER();
    const int z = blockIdx.z;
    if (rs && z == 0) {
        const int i = blockIdx.x * 256 + threadIdx.x;
        if (i < nrs) rs[i] = 0.0f;
    }
    const float* x = (z == 0) ? x0 : (z == 1) ? x1 : x2;
    uint8_t*   dst = (z == 0) ? d0 : (z == 1) ? d1 : d2;
    const int stride = (int)gridDim.x * 256;
    int u0 = blockIdx.x * 256 + threadIdx.x;

    for (; u0 + 3 * stride < nunits; u0 += 4 * stride) {
        float4 f[8];
#pragma unroll
        for (int k = 0; k < 4; ++k) {
            const int u = u0 + k * stride;
            const int r = u >> 7, j = u & 127;
            const float* p = x + ((size_t)r << 10) + (j << 3);
            f[2 * k]     = *(const float4*)p;
            f[2 * k + 1] = *(const float4*)(p + 4);
        }
#pragma unroll
        for (int k = 0; k < 4; ++k) {
            const int u = u0 + k * stride;
            const int r = u >> 7, j = u & 127;
            uint4 hv;
            hv.x = pkh2(__float2half(f[2*k].x),   __float2half(f[2*k].y));
            hv.y = pkh2(__float2half(f[2*k].z),   __float2half(f[2*k].w));
            hv.z = pkh2(__float2half(f[2*k+1].x), __float2half(f[2*k+1].y));
            hv.w = pkh2(__float2half(f[2*k+1].z), __float2half(f[2*k+1].w));
            const size_t blk = ((((size_t)(r >> 8)) << 4) + (j >> 3)) << 15;
            const uint32_t ro = (uint32_t)(r & 255) * 128 + (j & 7) * 16;
            *(uint4*)(dst + blk + SWZ128(ro)) = hv;
        }
    }
    for (; u0 < nunits; u0 += stride) {
        const int r = u0 >> 7, j = u0 & 127;
        const float4 f0 = *(const float4*)(x + ((size_t)r << 10) + (j << 3));
        const float4 f1 = *(const float4*)(x + ((size_t)r << 10) + (j << 3) + 4);
        uint4 hv;
        hv.x = pkh2(__float2half(f0.x), __float2half(f0.y));
        hv.y = pkh2(__float2half(f0.z), __float2half(f0.w));
        hv.z = pkh2(__float2half(f1.x), __float2half(f1.y));
        hv.w = pkh2(__float2half(f1.z), __float2half(f1.w));
        const size_t blk = ((((size_t)(r >> 8)) << 4) + (j >> 3)) << 15;
        const uint32_t ro = (uint32_t)(r & 255) * 128 + (j & 7) * 16;
        *(uint4*)(dst + blk + SWZ128(ro)) = hv;
    }
}

// ---------------------------------------------------------------------------
extern "C" void kernel_launch(void* const* d_in, const int* in_sizes, int n_in,
                              void* d_out, int out_size)
{
    (void)in_sizes; (void)n_in; (void)out_size;
    const float* q  = (const float*)d_in[0];
    const float* kx = (const float*)d_in[1];
    const float* vx = (const float*)d_in[2];
    const float* Wq = (const float*)d_in[3];
    const float* bq = (const float*)d_in[4];
    const float* Wk = (const float*)d_in[5];
    const float* bk = (const float*)d_in[6];
    const float* Wv = (const float*)d_in[7];
    const float* bv = (const float*)d_in[8];
    float* out = (float*)d_out;

    uint8_t *Xq, *Xk, *Xv, *Wqb, *Wkb, *Wvb, *Qb, *Kb, *Vt, *Pb;
    float* rs;
    cudaGetSymbolAddress((void**)&Xq,  g_Xq);  cudaGetSymbolAddress((void**)&Xk,  g_Xk);
    cudaGetSymbolAddress((void**)&Xv,  g_Xv);
    cudaGetSymbolAddress((void**)&Wqb, g_Wq);  cudaGetSymbolAddress((void**)&Wkb, g_Wk);
    cudaGetSymbolAddress((void**)&Wvb, g_Wv);
    cudaGetSymbolAddress((void**)&Qb,  g_Qb);  cudaGetSymbolAddress((void**)&Kb,  g_Kb);
    cudaGetSymbolAddress((void**)&Vt,  g_Vt);  cudaGetSymbolAddress((void**)&Pb,  g_Pb);
    cudaGetSymbolAddress((void**)&rs,  g_rs);

    cudaFuncSetAttribute(tc_gemm<1>, cudaFuncAttributeMaxDynamicSharedMemorySize, SMEM_TOTAL);
    cudaFuncSetAttribute(tc_gemm<3>, cudaFuncAttributeMaxDynamicSharedMemorySize, SMEM_TOTAL);
    cudaFuncSetAttribute(tc_gemm<4>, cudaFuncAttributeMaxDynamicSharedMemorySize, SMEM_TOTAL);

    // PDL launch attribute (applied to every kernel after the first)
    cudaLaunchAttribute pdl[1];
    pdl[0].id = cudaLaunchAttributeProgrammaticStreamSerialization;
    pdl[0].val.programmaticStreamSerializationAllowed = 1;

    // 1a. input splits (first kernel: plain launch)
    split3_k<<<dim3(512, 1, 3), 256>>>(q, kx, vx, Xq, Xk, Xv,
                                       NTOK * DIN / 8, nullptr, 0);

    // 1b. weight splits + rs zero: PDL, NO data dependence -> overlaps 1a
    {
        cudaLaunchConfig_t cfg{};
        cfg.gridDim = dim3(128, 1, 3); cfg.blockDim = dim3(256);
        cfg.dynamicSmemBytes = 0; cfg.stream = 0;
        cfg.attrs = pdl; cfg.numAttrs = 1;
        cudaLaunchKernelEx(&cfg, split3_k,
                           Wq, Wk, Wv, Wqb, Wkb, Wvb,
                           (int)(DM * DIN / 8), rs, (int)(BN * SEQ));
    }

    // 2. MERGED Q-proj + K-proj + Vt (768 tiles), PDL-gated on splits
    {
        cudaLaunchConfig_t cfg{};
        cfg.gridDim = dim3(768); cfg.blockDim = dim3(256);
        cfg.dynamicSmemBytes = SMEM_TOTAL; cfg.stream = 0;
        cfg.attrs = pdl; cfg.numAttrs = 1;
        cudaLaunchKernelEx(&cfg, tc_gemm<1>,
            (const uint8_t*)Xq, (const uint8_t*)Wqb,
            (const uint8_t*)Xk, (const uint8_t*)Wkb,
            (const uint8_t*)Wvb, (const uint8_t*)Xv,
            bq, bk, bv,
            (float*)nullptr, Qb, Kb, Vt, (float*)nullptr,
            (int)DIN, 1.0f, (size_t)0, (size_t)0, (size_t)0);
    }

    // 3. scores + exp + row sums -> fp16 P, PDL-gated on projections
    {
        cudaLaunchConfig_t cfg{};
        cfg.gridDim = dim3(SEQ / 256, SEQ / 256, BN); cfg.blockDim = dim3(256);
        cfg.dynamicSmemBytes = SMEM_TOTAL; cfg.stream = 0;
        cfg.attrs = pdl; cfg.numAttrs = 1;
        cudaLaunchKernelEx(&cfg, tc_gemm<3>,
            (const uint8_t*)Qb, (const uint8_t*)Kb,
            (const uint8_t*)nullptr, (const uint8_t*)nullptr,
            (const uint8_t*)nullptr, (const uint8_t*)nullptr,
            (const float*)nullptr, (const float*)nullptr, (const float*)nullptr,
            (float*)nullptr, Pb, (uint8_t*)nullptr, (uint8_t*)nullptr, rs,
            (int)DM, 0.03125f, (size_t)4194304u, (size_t)4194304u, (size_t)0);
    }

    // 4. O = (P * Vt^T) / rowsum, PDL-gated on scores
    {
        cudaLaunchConfig_t cfg{};
        cfg.gridDim = dim3(DM / 256, SEQ / 256, BN); cfg.blockDim = dim3(256);
        cfg.dynamicSmemBytes = SMEM_TOTAL; cfg.stream = 0;
        cfg.attrs = pdl; cfg.numAttrs = 1;
        cudaLaunchKernelEx(&cfg, tc_gemm<4>,
            (const uint8_t*)Pb, (const uint8_t*)Vt,
            (const uint8_t*)nullptr, (const uint8_t*)nullptr,
            (const uint8_t*)nullptr, (const uint8_t*)nullptr,
            (const float*)nullptr, (const float*)nullptr, (const float*)nullptr,
            out, (uint8_t*)nullptr, (uint8_t*)nullptr, (uint8_t*)nullptr, rs,
            (int)SEQ, 1.0f, (size_t)8388608u, (size_t)4194304u,
            (size_t)((size_t)SEQ * DM));
    }
}

// round 17
// speedup vs baseline: 1.1034x; 1.0194x over previous
#include <cuda_runtime.h>
#include <cuda_bf16.h>
#include <cuda_fp16.h>
#include <cstdint>

// ---------------------------------------------------------------------------
// Problem constants
// ---------------------------------------------------------------------------
#define BN   8
#define SEQ  2048
#define DIN  1024
#define DM   1024
#define NTOK (BN*SEQ)          // 16384

// ---------------------------------------------------------------------------
// Blocked fp16 operand layout (round-9/12 validated):
//   operand[row, k] stored as 32KB blocks indexed [row/256][k/64].
//   Block: 256 rows x 128B; row = 64 fp16 k-values, SW128-swizzled.
//   GEMM chunk (K=64) load = TWO contiguous 32KB cp.async.bulk copies.
// Round-17: bulk L2 prefetch of chunk c+5 (2 beyond the smem pipeline) so
//   bulk copies hit L2 instead of DRAM. PDL on all boundaries (round 16).
// ---------------------------------------------------------------------------
#define SWZ128(off) ((off) ^ (((off) >> 3) & 0x70))

__device__ uint8_t g_Xq[(size_t)NTOK*DIN*2];
__device__ uint8_t g_Xk[(size_t)NTOK*DIN*2];
__device__ uint8_t g_Xv[(size_t)NTOK*DIN*2];
__device__ uint8_t g_Wq[(size_t)DM*DIN*2];
__device__ uint8_t g_Wk[(size_t)DM*DIN*2];
__device__ uint8_t g_Wv[(size_t)DM*DIN*2];
__device__ uint8_t g_Qb[(size_t)NTOK*DM*2];          // 4MB/batch, nkc=16
__device__ uint8_t g_Kb[(size_t)NTOK*DM*2];
__device__ uint8_t g_Vt[(size_t)BN*DM*SEQ*2];        // rows=v, k=s, nkc=32, 4MB/batch
__device__ uint8_t g_Pb[(size_t)BN*SEQ*SEQ*2];       // rows=q, k=s, nkc=32, 8MB/batch
__device__ float   g_rs[(size_t)BN*SEQ];

// ---------------------------------------------------------------------------
// PDL primitives (sm_90+ PTX, fine under compute_103)
// ---------------------------------------------------------------------------
#define PDL_TRIGGER() asm volatile("griddepcontrol.launch_dependents;" ::: "memory")
#define PDL_WAIT()    asm volatile("griddepcontrol.wait;" ::: "memory")

// ---------------------------------------------------------------------------
// Helpers available on base compute_103
// ---------------------------------------------------------------------------
__device__ __forceinline__ uint32_t smem_u32(const void* p) {
    uint32_t a;
    asm("{ .reg .u64 t; cvta.to.shared.u64 t, %1; cvt.u32.u64 %0, t; }"
        : "=r"(a) : "l"(p));
    return a;
}
__device__ __forceinline__ void cp16(uint32_t dst, const void* src) {
    asm volatile("cp.async.cg.shared.global [%0], [%1], 16;" :: "r"(dst), "l"(src));
}
#define CP_COMMIT()  asm volatile("cp.async.commit_group;" ::: "memory")
#define CP_WAIT(N)   asm volatile("cp.async.wait_group %0;" :: "n"(N) : "memory")

__device__ __forceinline__ void mma16816h(float* c, const uint32_t* a,
                                          uint32_t b0, uint32_t b1) {
    asm volatile(
        "mma.sync.aligned.m16n8k16.row.col.f32.f16.f16.f32 "
        "{%0,%1,%2,%3}, {%4,%5,%6,%7}, {%8,%9}, {%0,%1,%2,%3};"
        : "+f"(c[0]), "+f"(c[1]), "+f"(c[2]), "+f"(c[3])
        : "r"(a[0]), "r"(a[1]), "r"(a[2]), "r"(a[3]), "r"(b0), "r"(b1));
}

__device__ __forceinline__ uint32_t pkh2(__half a, __half b) {
    __half2 t; t.x = a; t.y = b;
    return *(uint32_t*)&t;
}
// scalar fp16 store into blocked layout (fallback path)
__device__ __forceinline__ void store_blk1(uint8_t* base, int row, int k,
                                           int nkc, float v) {
    const size_t blk = (((size_t)(row >> 8)) * nkc + (k >> 6)) << 15;
    const uint32_t off = (uint32_t)(row & 255) * 128 + (k & 63) * 2;
    *(__half*)(base + blk + SWZ128(off)) = __float2half(v);
}

// bulk copy (UBLKCP): contiguous gmem -> smem, completion via mbarrier tx-bytes
__device__ __forceinline__ void bulk_ld(uint32_t dst, const void* src,
                                        uint32_t bytes, uint32_t mbar) {
    asm volatile(
        "cp.async.bulk.shared::cluster.global.mbarrier::complete_tx::bytes "
        "[%0], [%1], %2, [%3];"
        :: "r"(dst), "l"(src), "r"(bytes), "r"(mbar) : "memory");
}
// bulk L2 prefetch hint (no completion tracking)
__device__ __forceinline__ void bulk_pf(const void* src, uint32_t bytes) {
    asm volatile("cp.async.bulk.prefetch.L2.global [%0], %1;"
                 :: "l"(src), "r"(bytes) : "memory");
}
#define MBAR_INIT(addr, cnt) \
    asm volatile("mbarrier.init.shared.b64 [%0], %1;" :: "r"((uint32_t)(addr)), "r"((uint32_t)(cnt)) : "memory")
#define MBAR_EXPECT(addr, tx) \
    asm volatile("mbarrier.arrive.expect_tx.shared.b64 _, [%0], %1;" :: "r"((uint32_t)(addr)), "r"((uint32_t)(tx)) : "memory")
#define MBAR_WAIT(mbar, par) do { \
    uint32_t _m = (uint32_t)(mbar), _p = (uint32_t)(par), _d; \
    asm volatile("{\n\t.reg .pred p;\n\t" \
        "mbarrier.try_wait.parity.acquire.cta.shared::cta.b64 p, [%1], %2;\n\t" \
        "selp.b32 %0, 1, 0, p;\n\t}" : "=r"(_d) : "r"(_m), "r"(_p) : "memory"); \
    if (!_d) { \
        asm volatile("{\n\t.reg .pred P1;\n\t" \
            "WL_%=:\n\t" \
            "mbarrier.try_wait.parity.acquire.cta.shared::cta.b64 P1, [%0], %1, 0x989680;\n\t" \
            "@P1 bra.uni WD_%=;\n\tbra.uni WL_%=;\n\tWD_%=:\n\t}" \
            :: "r"(_m), "r"(_p) : "memory"); \
    } \
} while (0)

// ---------------------------------------------------------------------------
// tcgen05 helpers — ONLY compiled when the build has a compute_103a pass.
// ---------------------------------------------------------------------------
#if defined(__CUDA_ARCH_FEAT_SM103_ALL)
__device__ __forceinline__ uint32_t elect_one_pred() {
    uint32_t pred;
    asm volatile(
        "{\n\t.reg .pred p;\n\t"
        "elect.sync _|p, 0xFFFFFFFF;\n\t"
        "selp.b32 %0, 1, 0, p;\n\t}"
        : "=r"(pred));
    return pred;
}
#define TCGEN05_ALLOC(a, n) \
    asm volatile("tcgen05.alloc.cta_group::1.sync.aligned.shared::cta.b32 [%0], %1;" \
        :: "r"((uint32_t)(a)), "r"((uint32_t)(n)) : "memory")
#define TCGEN05_RELINQUISH() \
    asm volatile("tcgen05.relinquish_alloc_permit.cta_group::1.sync.aligned;")
#define TCGEN05_DEALLOC(t, n) \
    asm volatile("tcgen05.dealloc.cta_group::1.sync.aligned.b32 %0, %1;" :: "r"(t), "r"((uint32_t)(n)))
#define TCGEN05_COMMIT(m) \
    asm volatile("tcgen05.commit.cta_group::1.mbarrier::arrive::one.shared::cluster.b64 [%0];" \
        :: "r"((uint32_t)(m)) : "memory")
#define TCGEN05_WAIT_LD()    asm volatile("tcgen05.wait::ld.sync.aligned;" ::: "memory")
#define TCGEN05_FENCE_AFTER() asm volatile("tcgen05.fence::after_thread_sync;" ::: "memory")
#define TCGEN05_LD_32X32B_X32(r, ta) \
    asm volatile( \
        "tcgen05.ld.sync.aligned.32x32b.x32.b32 " \
        "{%0, %1, %2, %3, %4, %5, %6, %7, " \
        " %8, %9, %10, %11, %12, %13, %14, %15, " \
        " %16, %17, %18, %19, %20, %21, %22, %23, " \
        " %24, %25, %26, %27, %28, %29, %30, %31}, [%32];" \
        : "=r"((r)[0]),  "=r"((r)[1]),  "=r"((r)[2]),  "=r"((r)[3]), \
          "=r"((r)[4]),  "=r"((r)[5]),  "=r"((r)[6]),  "=r"((r)[7]), \
          "=r"((r)[8]),  "=r"((r)[9]),  "=r"((r)[10]), "=r"((r)[11]), \
          "=r"((r)[12]), "=r"((r)[13]), "=r"((r)[14]), "=r"((r)[15]), \
          "=r"((r)[16]), "=r"((r)[17]), "=r"((r)[18]), "=r"((r)[19]), \
          "=r"((r)[20]), "=r"((r)[21]), "=r"((r)[22]), "=r"((r)[23]), \
          "=r"((r)[24]), "=r"((r)[25]), "=r"((r)[26]), "=r"((r)[27]), \
          "=r"((r)[28]), "=r"((r)[29]), "=r"((r)[30]), "=r"((r)[31]) \
        : "r"(ta))
static constexpr uint64_t SMEM_DESC_BASE_SW128 =
    (uint64_t(2)  << 61) | (uint64_t(1) << 46) | (uint64_t(64) << 32) | (uint64_t(1) << 16);
#define MAKE_SMEM_DESC(ba) (SMEM_DESC_BASE_SW128 | ((uint64_t)((ba) >> 4) & 0x3FFF))
__device__ __forceinline__ void mma_f16_ss(uint32_t d, uint64_t ad, uint64_t bd,
                                           uint32_t idesc, bool acc) {
    uint32_t en = acc ? 1u : 0u;
    asm volatile(
        "{\n\t.reg .pred p;\n\t"
        "setp.ne.u32 p, %5, 0;\n\t"
        "tcgen05.mma.cta_group::1.kind::f16 [%0], %1, %2, %3, {%4, %4, %4, %4}, p;\n\t"
        "}"
        :: "r"(d), "l"(ad), "l"(bd), "r"(idesc), "r"(0u), "r"(en)
        : "memory");
}
#endif  // __CUDA_ARCH_FEAT_SM103_ALL

// ---------------------------------------------------------------------------
// GEMM: C[M,N] = A[M,K] * B[N,K]^T, single-pass fp16 operands (blocked).
// tcgen05: CTA 256x256, TK=64, two M=128 TMEM accumulators, 3-stage pipeline,
// 2x32KB bulk loads/chunk + L2 prefetch of chunk c+5, single-elected-thread
// mainloop, deferred MMA wait. Paired-LDTM epilogue. PDL trigger/wait.
// MODE 1: MERGED projections, 1-D grid of 768 tiles:
//   t<512  : Q/K proj (cls=t>>8): A=X?, B=W?, bias[n], out blocked nkc=16
//   t>=512 : Vt tile: A=Wv, B=Xv(batch), bias[m], out Vt nkc=32 (4MB/batch)
// MODE 3: e=expf(acc*alpha) f16 out + row-sum atomics [scores->P], nkc=32
// MODE 4: f32 out = acc / rowsum[m]  [PV]
// ---------------------------------------------------------------------------
constexpr int OFF_B  = 32768;
constexpr int STAGE  = 65536;                     // 32KB A + 32KB B
constexpr int SMEM_DATA = 1024;
constexpr int SMEM_TOTAL = SMEM_DATA + 3 * STAGE; // 197632

template <int MODE>
__global__ void __launch_bounds__(256, 1) tc_gemm(
    const uint8_t* __restrict__ Ab, const uint8_t* __restrict__ Bb,
    const uint8_t* __restrict__ A2b, const uint8_t* __restrict__ B2b,
    const uint8_t* __restrict__ A3b, const uint8_t* __restrict__ B3b,
    const float* __restrict__ bias, const float* __restrict__ bias2,
    const float* __restrict__ bias3,
    float* __restrict__ Cf, uint8_t* __restrict__ Cb, uint8_t* __restrict__ C2b,
    uint8_t* __restrict__ C3b,
    float* __restrict__ rs,
    int K, float alpha,
    size_t sAb, size_t sBb, size_t sC)
{
    extern __shared__ char smem[];
    const int tid = threadIdx.x;
    PDL_TRIGGER();                 // let the next kernel begin its prologue
    int m0, n0, cls = 0;
    size_t zb = 0;

    if (MODE == 1) {
        const int t = blockIdx.x;
        if (t < 512) {                       // Q/K projection tiles
            cls = t >> 8;
            const int r = t & 255;
            m0 = (r >> 2) << 8;              // token row tile (64)
            n0 = (r & 3) << 8;               // output-dim tile (4)
            if (cls == 1) { Ab = A2b; Bb = B2b; bias = bias2; Cb = C2b; }
        } else {                             // Vt tiles
            cls = 2;
            const int u = t - 512;
            zb = (size_t)(u >> 5);
            const int r = u & 31;
            m0 = (r >> 3) << 8;              // v tile (4)
            n0 = (r & 7) << 8;               // s tile (8)
            Ab = A3b; Bb = B3b + zb * 4194304u; bias = bias3; Cb = C3b;
        }
    } else {
        zb = blockIdx.z;
        m0 = blockIdx.y * 256;
        n0 = blockIdx.x * 256;
        Ab += zb * sAb;  Bb += zb * sBb;
    }
    const int NC = K >> 6;                    // 64-k chunks
    const size_t blkA0 = ((size_t)(m0 >> 8)) * NC;
    const size_t blkB0 = ((size_t)(n0 >> 8)) * NC;

#if defined(__CUDA_ARCH_FEAT_SM103_ALL)
    // ======================= tcgen05 path (sm_103a) ========================
    const uint32_t sb = smem_u32(smem);

    if (tid < 32) TCGEN05_ALLOC(sb + 0, 512);
    if (tid >= 32 && tid < 64) TCGEN05_RELINQUISH();
    if (tid == 0) {
#pragma unroll
        for (int s = 0; s < 3; ++s) {
            MBAR_INIT(sb + 8  + 8 * s, 1);   // full (tx-based)
            MBAR_INIT(sb + 32 + 8 * s, 1);   // mma done
        }
    }
    __syncthreads();
    uint32_t tmem;
    asm volatile("ld.shared.b32 %0, [%1];" : "=r"(tmem) : "r"(sb + 0));

    PDL_WAIT();                    // producer grid's memory now visible

    constexpr uint32_t IDESC =
        (1u << 4) | ((256 / 8) << 17) | ((128 / 16) << 24);

    if (tid < 32 && elect_one_pred()) {
        auto load_chunk = [&](int kc, int st) {
            const uint32_t full = sb + 8 + 8 * st;
            const uint32_t base = sb + SMEM_DATA + st * STAGE;
            MBAR_EXPECT(full, STAGE);
            bulk_ld(base,         Ab + ((blkA0 + kc) << 15), 32768, full);
            bulk_ld(base + OFF_B, Bb + ((blkB0 + kc) << 15), 32768, full);
        };
        auto prefetch_chunk = [&](int kc) {
            bulk_pf(Ab + ((blkA0 + kc) << 15), 32768);
            bulk_pf(Bb + ((blkB0 + kc) << 15), 32768);
        };

        load_chunk(0, 0);
        if (NC > 1) load_chunk(1, 1);
        if (NC > 2) load_chunk(2, 2);
        // warm L2 ahead of the 3-deep pipeline
        if (NC > 3) prefetch_chunk(3);
        if (NC > 4) prefetch_chunk(4);

        int fph[3] = {0, 0, 0}, mph[3] = {0, 0, 0};
        for (int c = 0; c < NC; ++c) {
            const int st = c % 3;
            MBAR_WAIT(sb + 8 + 8 * st, fph[st]);
            fph[st] ^= 1;

            if (c + 5 < NC) prefetch_chunk(c + 5);

            const uint32_t base = sb + SMEM_DATA + st * STAGE;
            const uint64_t daA0 = MAKE_SMEM_DESC(base);
            const uint64_t daA1 = MAKE_SMEM_DESC(base + 16384);
            const uint64_t db   = MAKE_SMEM_DESC(base + OFF_B);
#pragma unroll
            for (int half = 0; half < 2; ++half) {
                const uint64_t da = half ? daA1 : daA0;
                const uint32_t dt = tmem + half * 256;
#pragma unroll
                for (int ks = 0; ks < 4; ++ks)
                    mma_f16_ss(dt, da + ks * 2, db + ks * 2, IDESC,
                               !(c == 0 && ks == 0));
            }
            TCGEN05_COMMIT(sb + 32 + 8 * st);

            if (c > 0) {
                const int sp = (c - 1) % 3;
                MBAR_WAIT(sb + 32 + 8 * sp, mph[sp]);
                mph[sp] ^= 1;
                if (c + 2 < NC) load_chunk(c + 2, sp);
            }
        }
        MBAR_WAIT(sb + 32 + 8 * ((NC - 1) % 3), mph[(NC - 1) % 3]);
    }
    __syncthreads();
    TCGEN05_FENCE_AFTER();

    // epilogue: warps 0-3 -> D0 (rows 0-127), warps 4-7 -> D1 (rows 128-255)
    {
        const int half = tid >> 7;
        const int w4   = (tid >> 5) & 3;
        const int lid  = tid & 31;
        const int m    = m0 + half * 128 + w4 * 32 + lid;
        const uint32_t dt = tmem + half * 256;
        float inv = 1.0f, lsum = 0.0f, bm = 0.0f;
        if (MODE == 4) inv = 1.0f / rs[zb * SEQ + m];
        if (MODE == 1 && cls == 2) bm = bias[m];
        for (int j0 = 0; j0 < 256; j0 += 64) {
            uint32_t r[64];
            TCGEN05_LD_32X32B_X32(r,      dt + j0);
            TCGEN05_LD_32X32B_X32(r + 32, dt + j0 + 32);
            TCGEN05_WAIT_LD();
            if (MODE == 4) {
                float4* dst = (float4*)(Cf + zb * sC + (size_t)m * DM + n0 + j0);
#pragma unroll
                for (int i = 0; i < 16; ++i) {
                    float4 v;
                    v.x = __uint_as_float(r[4 * i + 0]) * inv;
                    v.y = __uint_as_float(r[4 * i + 1]) * inv;
                    v.z = __uint_as_float(r[4 * i + 2]) * inv;
                    v.w = __uint_as_float(r[4 * i + 3]) * inv;
                    dst[i] = v;
                }
            } else {   // MODE 1 / 3: blocked fp16 store (64 vals = 128B row)
                uint32_t H[32];
#pragma unroll
                for (int i = 0; i < 64; i += 2) {
                    float v0, v1;
                    if (MODE == 3) {
                        v0 = __expf(__uint_as_float(r[i])     * alpha);
                        v1 = __expf(__uint_as_float(r[i + 1]) * alpha);
                        lsum += v0 + v1;
                    } else if (cls < 2) {
                        v0 = __uint_as_float(r[i])     + bias[n0 + j0 + i];
                        v1 = __uint_as_float(r[i + 1]) + bias[n0 + j0 + i + 1];
                    } else {
                        v0 = __uint_as_float(r[i])     + bm;
                        v1 = __uint_as_float(r[i + 1]) + bm;
                    }
                    H[i >> 1] = pkh2(__float2half(v0), __float2half(v1));
                }
                uint8_t* base;
                size_t blk;
                const int row = m & 255;
                if (MODE == 1 && cls < 2) {   // Q/K: 4MB/batch(by m), nkc = 16
                    base = Cb + (size_t)(m >> 11) * 4194304u;
                    blk  = ((((size_t)((m & 2047) >> 8)) * 16) + ((n0 + j0) >> 6)) << 15;
                } else if (MODE == 3) {       // P: 8MB/batch, nkc = 32
                    base = Cb + zb * 8388608u;
                    blk  = ((((size_t)(m >> 8)) * 32) + ((n0 + j0) >> 6)) << 15;
                } else {                      // Vt: 4MB/batch, nkc = 32
                    base = Cb + zb * 4194304u;
                    blk  = ((((size_t)(m >> 8)) * 32) + ((n0 + j0) >> 6)) << 15;
                }
#pragma unroll
                for (int q = 0; q < 8; ++q) {
                    uint4 hv;
                    hv.x = H[4*q]; hv.y = H[4*q+1]; hv.z = H[4*q+2]; hv.w = H[4*q+3];
                    *(uint4*)(base + blk +
                              SWZ128((uint32_t)row * 128 + q * 16)) = hv;
                }
            }
        }
        if (MODE == 3) atomicAdd(&rs[zb * SEQ + m], lsum);
    }
    __syncthreads();
    if (tid < 32) TCGEN05_DEALLOC(tmem, 512);

#elif defined(__CUDA_ARCH__)
    // ================= mma.sync fallback (base compute_103) =================
    // Correctness insurance only (sm_103a cubin is the one that runs).
    constexpr int STR = 20;
    constexpr int TILE_W = 128 * STR;
    constexpr int STAGE_W = 2 * TILE_W;
    const uint32_t sbase = smem_u32(smem);
    const int lane = tid & 31, wid = tid >> 5;
    const int wm = wid >> 1, wn = wid & 1;
    const int g = lane >> 2, tg = lane & 3;
    const int NC32 = K >> 5;

    PDL_WAIT();

    auto load_chunk = [&](int c32, int st, int mbase, int nbase) {
        const int q = tid & 3, r0 = tid >> 2;
        const uint32_t dst0 = sbase + st * STAGE_W * 4;
        const int kc = c32 >> 1, h = c32 & 1;
#pragma unroll
        for (int i = 0; i < 2; ++i) {
            const int ra = mbase + r0 + 64 * i;
            const int rb = nbase + r0 + 64 * i;
            const uint32_t ro = (uint32_t)((r0 + 64 * i) * STR + q * 4) * 4;
            const size_t ba = (((size_t)(ra >> 8)) * NC + kc) << 15;
            const size_t bb = (((size_t)(rb >> 8)) * NC + kc) << 15;
            const uint32_t oa = (uint32_t)(ra & 255) * 128 + h * 64 + q * 16;
            const uint32_t ob = (uint32_t)(rb & 255) * 128 + h * 64 + q * 16;
            cp16(dst0 + ro,                Ab + ba + SWZ128(oa));
            cp16(dst0 + TILE_W * 4 + ro,   Bb + bb + SWZ128(ob));
        }
    };

    for (int mh = 0; mh < 2; ++mh) {
        const int mb0 = m0 + mh * 128;
        for (int np = 0; np < 2; ++np) {
            const int nb0 = n0 + np * 128;

            float acc[2][8][4];
#pragma unroll
            for (int a = 0; a < 2; ++a)
#pragma unroll
                for (int b = 0; b < 8; ++b)
#pragma unroll
                    for (int c = 0; c < 4; ++c) acc[a][b][c] = 0.0f;

            load_chunk(0, 0, mb0, nb0); CP_COMMIT();

            for (int c = 0; c < NC32; ++c) {
                const int st = c & 1;
                if (c + 1 < NC32) { load_chunk(c + 1, st ^ 1, mb0, nb0); CP_COMMIT(); CP_WAIT(1); }
                else              { CP_WAIT(0); }
                __syncthreads();

                const uint32_t* s0 = (const uint32_t*)smem + st * STAGE_W;
#pragma unroll
                for (int ks = 0; ks < 2; ++ks) {
                    uint32_t af[2][4];
#pragma unroll
                    for (int mt = 0; mt < 2; ++mt) {
                        const int rb = wm * 32 + mt * 16;
                        const uint32_t* pa = s0 + (rb + g) * STR + ks * 8 + tg;
                        af[mt][0] = pa[0];           af[mt][2] = pa[4];
                        af[mt][1] = pa[8 * STR];     af[mt][3] = pa[8 * STR + 4];
                    }
#pragma unroll
                    for (int nt = 0; nt < 8; ++nt) {
                        const int nb = wn * 64 + nt * 8;
                        const uint32_t* pb = s0 + TILE_W + (nb + g) * STR + ks * 8 + tg;
                        const uint32_t b0 = pb[0], b1 = pb[4];
#pragma unroll
                        for (int mt = 0; mt < 2; ++mt)
                            mma16816h(acc[mt][nt], af[mt], b0, b1);
                    }
                }
                __syncthreads();
            }

#pragma unroll
            for (int mt = 0; mt < 2; ++mt) {
#pragma unroll
                for (int nt = 0; nt < 8; ++nt) {
                    const int m1 = mb0 + wm * 32 + mt * 16 + g;
                    const int m2 = m1 + 8;
                    const int n  = nb0 + wn * 64 + nt * 8 + tg * 2;
                    const float* a = acc[mt][nt];
                    if (MODE == 4) {
                        const float i1 = 1.0f / rs[zb * SEQ + m1];
                        const float i2 = 1.0f / rs[zb * SEQ + m2];
                        float2 v0; v0.x = a[0] * i1; v0.y = a[1] * i1;
                        float2 v1; v1.x = a[2] * i2; v1.y = a[3] * i2;
                        *(float2*)(Cf + zb * sC + (size_t)m1 * DM + n) = v0;
                        *(float2*)(Cf + zb * sC + (size_t)m2 * DM + n) = v1;
                    } else if (MODE == 1 && cls < 2) {
#pragma unroll
                        for (int e = 0; e < 4; ++e) {
                            const int m = (e < 2) ? m1 : m2;
                            const int nn = n + (e & 1);
                            store_blk1(Cb + (size_t)(m >> 11) * 4194304u,
                                       m & 2047, nn, 16, a[e] + bias[nn]);
                        }
                    } else if (MODE == 3) {
                        float e0 = __expf(a[0] * alpha), e1 = __expf(a[1] * alpha);
                        float e2 = __expf(a[2] * alpha), e3 = __expf(a[3] * alpha);
                        atomicAdd(&rs[zb * SEQ + m1], e0 + e1);
                        atomicAdd(&rs[zb * SEQ + m2], e2 + e3);
                        uint8_t* base = Cb + zb * 8388608u;
                        store_blk1(base, m1, n,     32, e0);
                        store_blk1(base, m1, n + 1, 32, e1);
                        store_blk1(base, m2, n,     32, e2);
                        store_blk1(base, m2, n + 1, 32, e3);
                    } else {  // MODE 1, cls == 2 (Vt)
                        uint8_t* base = Cb + zb * 4194304u;
#pragma unroll
                        for (int e = 0; e < 4; ++e) {
                            const int m = (e < 2) ? m1 : m2;
                            const int nn = n + (e & 1);
                            store_blk1(base, m, nn, 32, a[e] + bias[m]);
                        }
                    }
                }
            }
            __syncthreads();
        }
    }
#endif
}

// ---------------------------------------------------------------------------
// f32 -> blocked fp16 (K fixed = 1024; nkc = 16). z selects among 3 tensors.
// 4 units per iteration, loads front-loaded (MLP=8). Optionally zeros rs.
// Reads only harness inputs -> no PDL wait; triggers for downstream overlap.
// ---------------------------------------------------------------------------
__global__ void __launch_bounds__(256) split3_k(
    const float* __restrict__ x0, const float* __restrict__ x1,
    const float* __restrict__ x2,
    uint8_t* __restrict__ d0, uint8_t* __restrict__ d1,
    uint8_t* __restrict__ d2, int nunits,
    float* __restrict__ rs, int nrs)
{
    PDL_TRIGGER();
    const int z = blockIdx.z;
    if (rs && z == 0) {
        const int i = blockIdx.x * 256 + threadIdx.x;
        if (i < nrs) rs[i] = 0.0f;
    }
    const float* x = (z == 0) ? x0 : (z == 1) ? x1 : x2;
    uint8_t*   dst = (z == 0) ? d0 : (z == 1) ? d1 : d2;
    const int stride = (int)gridDim.x * 256;
    int u0 = blockIdx.x * 256 + threadIdx.x;

    for (; u0 + 3 * stride < nunits; u0 += 4 * stride) {
        float4 f[8];
#pragma unroll
        for (int k = 0; k < 4; ++k) {
            const int u = u0 + k * stride;
            const int r = u >> 7, j = u & 127;
            const float* p = x + ((size_t)r << 10) + (j << 3);
            f[2 * k]     = *(const float4*)p;
            f[2 * k + 1] = *(const float4*)(p + 4);
        }
#pragma unroll
        for (int k = 0; k < 4; ++k) {
            const int u = u0 + k * stride;
            const int r = u >> 7, j = u & 127;
            uint4 hv;
            hv.x = pkh2(__float2half(f[2*k].x),   __float2half(f[2*k].y));
            hv.y = pkh2(__float2half(f[2*k].z),   __float2half(f[2*k].w));
            hv.z = pkh2(__float2half(f[2*k+1].x), __float2half(f[2*k+1].y));
            hv.w = pkh2(__float2half(f[2*k+1].z), __float2half(f[2*k+1].w));
            const size_t blk = ((((size_t)(r >> 8)) << 4) + (j >> 3)) << 15;
            const uint32_t ro = (uint32_t)(r & 255) * 128 + (j & 7) * 16;
            *(uint4*)(dst + blk + SWZ128(ro)) = hv;
        }
    }
    for (; u0 < nunits; u0 += stride) {
        const int r = u0 >> 7, j = u0 & 127;
        const float4 f0 = *(const float4*)(x + ((size_t)r << 10) + (j << 3));
        const float4 f1 = *(const float4*)(x + ((size_t)r << 10) + (j << 3) + 4);
        uint4 hv;
        hv.x = pkh2(__float2half(f0.x), __float2half(f0.y));
        hv.y = pkh2(__float2half(f0.z), __float2half(f0.w));
        hv.z = pkh2(__float2half(f1.x), __float2half(f1.y));
        hv.w = pkh2(__float2half(f1.z), __float2half(f1.w));
        const size_t blk = ((((size_t)(r >> 8)) << 4) + (j >> 3)) << 15;
        const uint32_t ro = (uint32_t)(r & 255) * 128 + (j & 7) * 16;
        *(uint4*)(dst + blk + SWZ128(ro)) = hv;
    }
}

// ---------------------------------------------------------------------------
extern "C" void kernel_launch(void* const* d_in, const int* in_sizes, int n_in,
                              void* d_out, int out_size)
{
    (void)in_sizes; (void)n_in; (void)out_size;
    const float* q  = (const float*)d_in[0];
    const float* kx = (const float*)d_in[1];
    const float* vx = (const float*)d_in[2];
    const float* Wq = (const float*)d_in[3];
    const float* bq = (const float*)d_in[4];
    const float* Wk = (const float*)d_in[5];
    const float* bk = (const float*)d_in[6];
    const float* Wv = (const float*)d_in[7];
    const float* bv = (const float*)d_in[8];
    float* out = (float*)d_out;

    uint8_t *Xq, *Xk, *Xv, *Wqb, *Wkb, *Wvb, *Qb, *Kb, *Vt, *Pb;
    float* rs;
    cudaGetSymbolAddress((void**)&Xq,  g_Xq);  cudaGetSymbolAddress((void**)&Xk,  g_Xk);
    cudaGetSymbolAddress((void**)&Xv,  g_Xv);
    cudaGetSymbolAddress((void**)&Wqb, g_Wq);  cudaGetSymbolAddress((void**)&Wkb, g_Wk);
    cudaGetSymbolAddress((void**)&Wvb, g_Wv);
    cudaGetSymbolAddress((void**)&Qb,  g_Qb);  cudaGetSymbolAddress((void**)&Kb,  g_Kb);
    cudaGetSymbolAddress((void**)&Vt,  g_Vt);  cudaGetSymbolAddress((void**)&Pb,  g_Pb);
    cudaGetSymbolAddress((void**)&rs,  g_rs);

    cudaFuncSetAttribute(tc_gemm<1>, cudaFuncAttributeMaxDynamicSharedMemorySize, SMEM_TOTAL);
    cudaFuncSetAttribute(tc_gemm<3>, cudaFuncAttributeMaxDynamicSharedMemorySize, SMEM_TOTAL);
    cudaFuncSetAttribute(tc_gemm<4>, cudaFuncAttributeMaxDynamicSharedMemorySize, SMEM_TOTAL);

    // PDL launch attribute (applied to every kernel after the first)
    cudaLaunchAttribute pdl[1];
    pdl[0].id = cudaLaunchAttributeProgrammaticStreamSerialization;
    pdl[0].val.programmaticStreamSerializationAllowed = 1;

    // 1a. input splits (first kernel: plain launch)
    split3_k<<<dim3(512, 1, 3), 256>>>(q, kx, vx, Xq, Xk, Xv,
                                       NTOK * DIN / 8, nullptr, 0);

    // 1b. weight splits + rs zero: PDL, NO data dependence -> overlaps 1a
    {
        cudaLaunchConfig_t cfg{};
        cfg.gridDim = dim3(128, 1, 3); cfg.blockDim = dim3(256);
        cfg.dynamicSmemBytes = 0; cfg.stream = 0;
        cfg.attrs = pdl; cfg.numAttrs = 1;
        cudaLaunchKernelEx(&cfg, split3_k,
                           Wq, Wk, Wv, Wqb, Wkb, Wvb,
                           (int)(DM * DIN / 8), rs, (int)(BN * SEQ));
    }

    // 2. MERGED Q-proj + K-proj + Vt (768 tiles), PDL-gated on splits
    {
        cudaLaunchConfig_t cfg{};
        cfg.gridDim = dim3(768); cfg.blockDim = dim3(256);
        cfg.dynamicSmemBytes = SMEM_TOTAL; cfg.stream = 0;
        cfg.attrs = pdl; cfg.numAttrs = 1;
        cudaLaunchKernelEx(&cfg, tc_gemm<1>,
            (const uint8_t*)Xq, (const uint8_t*)Wqb,
            (const uint8_t*)Xk, (const uint8_t*)Wkb,
            (const uint8_t*)Wvb, (const uint8_t*)Xv,
            bq, bk, bv,
            (float*)nullptr, Qb, Kb, Vt, (float*)nullptr,
            (int)DIN, 1.0f, (size_t)0, (size_t)0, (size_t)0);
    }

    // 3. scores + exp + row sums -> fp16 P, PDL-gated on projections
    {
        cudaLaunchConfig_t cfg{};
        cfg.gridDim = dim3(SEQ / 256, SEQ / 256, BN); cfg.blockDim = dim3(256);
        cfg.dynamicSmemBytes = SMEM_TOTAL; cfg.stream = 0;
        cfg.attrs = pdl; cfg.numAttrs = 1;
        cudaLaunchKernelEx(&cfg, tc_gemm<3>,
            (const uint8_t*)Qb, (const uint8_t*)Kb,
            (const uint8_t*)nullptr, (const uint8_t*)nullptr,
            (const uint8_t*)nullptr, (const uint8_t*)nullptr,
            (const float*)nullptr, (const float*)nullptr, (const float*)nullptr,
            (float*)nullptr, Pb, (uint8_t*)nullptr, (uint8_t*)nullptr, rs,
            (int)DM, 0.03125f, (size_t)4194304u, (size_t)4194304u, (size_t)0);
    }

    // 4. O = (P * Vt^T) / rowsum, PDL-gated on scores
    {
        cudaLaunchConfig_t cfg{};
        cfg.gridDim = dim3(DM / 256, SEQ / 256, BN); cfg.blockDim = dim3(256);
        cfg.dynamicSmemBytes = SMEM_TOTAL; cfg.stream = 0;
        cfg.attrs = pdl; cfg.numAttrs = 1;
        cudaLaunchKernelEx(&cfg, tc_gemm<4>,
            (const uint8_t*)Pb, (const uint8_t*)Vt,
            (const uint8_t*)nullptr, (const uint8_t*)nullptr,
            (const uint8_t*)nullptr, (const uint8_t*)nullptr,
            (const float*)nullptr, (const float*)nullptr, (const float*)nullptr,
            out, (uint8_t*)nullptr, (uint8_t*)nullptr, (uint8_t*)nullptr, rs,
            (int)SEQ, 1.0f, (size_t)8388608u, (size_t)4194304u,
            (size_t)((size_t)SEQ * DM));
    }
}